// round 14
// baseline (speedup 1.0000x reference)
#include <cuda_runtime.h>

typedef unsigned long long u64;
#define NPOS 65536
#define NPOSf 65536.0f
#define NPART 16
#define SBST 36

// persistent scratch (device globals)
__device__ float  g_xp[32 * NPOS];              // residual stream x, [ch][pos]
__device__ float  g_rp[32 * NPOS];              // pre-BN layer output r, [ch][pos]
__device__ float4 g_xf[8 * NPOS];               // final x, channel quads
__device__ float  g_z[128 * NPOS];              // end_conv1 output
__device__ float  g_statp[NPART][42][2][128];   // partitioned stats

__device__ __forceinline__ float* stat_ptr(int part, int op, int kind) {
    return &g_statp[part][op][kind][0];
}

__device__ __forceinline__ void fma2(u64 &d, u64 a, u64 b, u64 c) {
    asm("fma.rn.f32x2 %0, %1, %2, %3;" : "=l"(d) : "l"(a), "l"(b), "l"(c));
}
__device__ __forceinline__ u64 pack2(float f) {
    u64 r; unsigned b = __float_as_uint(f);
    asm("mov.b64 %0, {%1, %1};" : "=l"(r) : "r"(b));
    return r;
}
__device__ __forceinline__ float lo2(u64 v) { return __uint_as_float((unsigned)v); }
__device__ __forceinline__ float hi2(u64 v) { return __uint_as_float((unsigned)(v >> 32)); }

__device__ __forceinline__ float mishf(float v) {
    float u = __expf(fminf(fmaxf(v, -20.0f), 20.0f));
    float w = fmaf(u, u, u + u);
    return v * __fdividef(w, w + 2.0f);
}

// mish(a) and mish(-a) sharing one exp
__device__ __forceinline__ void mish_pair(float a, float &mp, float &mn) {
    float ac = fminf(fmaxf(a, -20.0f), 20.0f);
    float u = __expf(ac);
    float A = fmaf(u, u, u + u);
    mp = a * __fdividef(A, A + 2.0f);
    float B = fmaf(2.0f, u, 1.0f);
    mn = -a * __fdividef(B, fmaf(u + u, u, B));
}

// ---- tf32 helpers ----
__device__ __forceinline__ unsigned cvt_tf32(float f) {
    unsigned r; asm("cvt.rna.tf32.f32 %0, %1;" : "=r"(r) : "f"(f)); return r;
}
__device__ __forceinline__ void split_tf32(float f, unsigned &hi, unsigned &lo) {
    hi = cvt_tf32(f);
    lo = cvt_tf32(f - __uint_as_float(hi));
}
__device__ __forceinline__ void mma_tf32(float* c, const unsigned* a,
                                         unsigned b0, unsigned b1) {
    asm("mma.sync.aligned.m16n8k8.row.col.f32.tf32.tf32.f32 "
        "{%0,%1,%2,%3}, {%4,%5,%6,%7}, {%8,%9}, {%0,%1,%2,%3};"
        : "+f"(c[0]), "+f"(c[1]), "+f"(c[2]), "+f"(c[3])
        : "r"(a[0]), "r"(a[1]), "r"(a[2]), "r"(a[3]), "r"(b0), "r"(b1));
}

// legacy reduction (k_start, 256 threads)
template<int BS>
__device__ __forceinline__ void reduce_stats(float* red, float* part1, float* part2,
                                             const float* vals, int tid,
                                             int prt, int op, int coff) {
    __syncthreads();
    #pragma unroll
    for (int c = 0; c < 32; c++) red[tid * 34 + c] = vals[c];
    __syncthreads();
    {
        int c = tid & 31, seg = tid >> 5;
        int base = seg * 32;
        float s = 0.f, q = 0.f;
        #pragma unroll
        for (int r = 0; r < 32; r++) {
            float v = red[(base + r) * 34 + c];
            s += v;
            q = fmaf(v, v, q);
        }
        part1[seg * 32 + c] = s;
        part2[seg * 32 + c] = q;
    }
    __syncthreads();
    if (tid < 64) {
        int c = tid & 31, kind = tid >> 5;
        const float* pp = kind ? part2 : part1;
        float t = 0.f;
        #pragma unroll
        for (int sg = 0; sg < BS / 32; sg++) t += pp[sg * 32 + c];
        atomicAdd(stat_ptr(prt, op, kind) + coff + c, t);
    }
}

// float4-vectorized reduction for 64-thread blocks; vals[32] per thread.
__device__ __forceinline__ void reduce64(float4* red4, float4* ps, float4* pq,
                                         const float* vals, int tid,
                                         int prt, int op) {
    __syncthreads();
    #pragma unroll
    for (int q = 0; q < 8; q++)
        red4[q * 65 + tid] = make_float4(vals[4 * q], vals[4 * q + 1],
                                         vals[4 * q + 2], vals[4 * q + 3]);
    __syncthreads();
    {
        int q = tid & 7, seg = tid >> 3;
        float4 s = make_float4(0.f, 0.f, 0.f, 0.f);
        float4 sq = make_float4(0.f, 0.f, 0.f, 0.f);
        #pragma unroll
        for (int r = 0; r < 8; r++) {
            float4 v = red4[q * 65 + seg * 8 + r];
            s.x += v.x; s.y += v.y; s.z += v.z; s.w += v.w;
            sq.x = fmaf(v.x, v.x, sq.x);
            sq.y = fmaf(v.y, v.y, sq.y);
            sq.z = fmaf(v.z, v.z, sq.z);
            sq.w = fmaf(v.w, v.w, sq.w);
        }
        ps[seg * 8 + q] = s;
        pq[seg * 8 + q] = sq;
    }
    __syncthreads();
    {
        int c = tid & 31, kind = tid >> 5;
        int quad = c >> 2, comp = c & 3;
        const float* base = (const float*)(kind ? pq : ps);
        float t = 0.f;
        #pragma unroll
        for (int seg = 0; seg < 8; seg++)
            t += base[(seg * 8 + quad) * 4 + comp];
        atomicAdd(stat_ptr(prt, op, kind) + c, t);
    }
}

// combine partitioned stats -> BN scale/shift (threads 0..31)
__device__ __forceinline__ void bn_combine32(const float* g, const float* b, int op,
                                             float* s_scale, float* s_shift, int tid) {
    if (tid < 32) {
        float s = 0.f, q = 0.f;
        #pragma unroll
        for (int pp = 0; pp < NPART; pp++) {
            s += g_statp[pp][op][0][tid];
            q += g_statp[pp][op][1][tid];
        }
        float m = s * (1.0f / NPOSf);
        float var = q * (1.0f / NPOSf) - m * m;
        float inv = rsqrtf(var + 1e-5f);
        float sc = g[tid] * inv;
        s_scale[tid] = sc;
        s_shift[tid] = b[tid] - m * sc;
    }
}

// full-width paired gate(16x32)->concat-mish->res(32x32) (k_start only)
__device__ __forceinline__ void gate_res_p(const float* xn, float* rn,
                                           const float* s_gw, const float* s_gb,
                                           const float* s_rw, const float* s_rb) {
    u64 accg[8];
    #pragma unroll
    for (int jp = 0; jp < 8; jp++) accg[jp] = *(const u64*)&s_gb[2 * jp];
    const ulonglong2* gw2 = (const ulonglong2*)s_gw;
    #pragma unroll
    for (int k = 0; k < 32; k++) {
        u64 xk = pack2(xn[k]);
        #pragma unroll
        for (int m = 0; m < 4; m++) {
            ulonglong2 w = gw2[k * 4 + m];
            fma2(accg[2 * m],     w.x, xk, accg[2 * m]);
            fma2(accg[2 * m + 1], w.y, xk, accg[2 * m + 1]);
        }
    }
    float cm[32];
    #pragma unroll
    for (int jp = 0; jp < 8; jp++) {
        float a0 = lo2(accg[jp]), a1 = hi2(accg[jp]);
        mish_pair(a0, cm[2 * jp],     cm[2 * jp + 16]);
        mish_pair(a1, cm[2 * jp + 1], cm[2 * jp + 17]);
    }
    u64 accr[16];
    #pragma unroll
    for (int cp = 0; cp < 16; cp++) accr[cp] = *(const u64*)&s_rb[2 * cp];
    const ulonglong2* rw2 = (const ulonglong2*)s_rw;
    #pragma unroll
    for (int k = 0; k < 32; k++) {
        u64 ck = pack2(cm[k]);
        #pragma unroll
        for (int m = 0; m < 8; m++) {
            ulonglong2 w = rw2[k * 8 + m];
            fma2(accr[2 * m],     w.x, ck, accr[2 * m]);
            fma2(accr[2 * m + 1], w.y, ck, accr[2 * m + 1]);
        }
    }
    #pragma unroll
    for (int cp = 0; cp < 16; cp++) {
        rn[2 * cp]     = lo2(accr[cp]);
        rn[2 * cp + 1] = hi2(accr[cp]);
    }
}

__global__ void k_prep() {
    int idx = blockIdx.x * 512 + threadIdx.x;
    float* st = &g_statp[0][0][0][0];
    if (idx < NPART * 42 * 2 * 128) st[idx] = 0.f;
}

// start conv (32x256) + layer-0 gate/res + stats[0]
__global__ __launch_bounds__(256, 2) void k_start(
    const float* __restrict__ xin,
    const float* __restrict__ start_w, const float* __restrict__ start_b,
    const float* __restrict__ gate_w, const float* __restrict__ gate_b,
    const float* __restrict__ res_w, const float* __restrict__ res_b)
{
    __shared__ __align__(16) float s_red[256 * 34];
    __shared__ float s_p1[256], s_p2[256];
    __shared__ __align__(16) float s_gw[512];
    __shared__ __align__(16) float s_rw[1024];
    __shared__ __align__(8) float s_gb[16];
    __shared__ __align__(8) float s_rb[32];
    __shared__ __align__(8) float s_sb[32];

    int tid = threadIdx.x;
    int p = blockIdx.x * 256 + tid;
    int prt = blockIdx.x & (NPART - 1);

    for (int idx = tid; idx < 8192; idx += 256) {
        int k = idx >> 5, c = idx & 31;
        s_red[k * 32 + c] = start_w[c * 256 + k];
    }
    for (int i = tid; i < 512; i += 256)  { int j = i & 15, k = i >> 4; s_gw[i] = gate_w[j * 32 + k]; }
    for (int i = tid; i < 1024; i += 256) { int c = i & 31, k = i >> 5; s_rw[i] = res_w[c * 32 + k]; }
    if (tid < 16) s_gb[tid] = gate_b[tid];
    if (tid >= 32 && tid < 64) s_rb[tid - 32] = res_b[tid - 32];
    if (tid >= 64 && tid < 96) s_sb[tid - 64] = start_b[tid - 64];
    __syncthreads();

    u64 acc[16];
    #pragma unroll
    for (int cp = 0; cp < 16; cp++) acc[cp] = *(const u64*)&s_sb[2 * cp];
    const float* xp = xin + (size_t)(p & 7) * (256 * 8192) + (p >> 3);
    const ulonglong2* swT2 = (const ulonglong2*)s_red;
    #pragma unroll 4
    for (int k = 0; k < 256; k++) {
        u64 xk = pack2(xp[k * 8192]);
        #pragma unroll
        for (int m = 0; m < 8; m++) {
            ulonglong2 w = swT2[k * 8 + m];
            fma2(acc[2 * m],     w.x, xk, acc[2 * m]);
            fma2(acc[2 * m + 1], w.y, xk, acc[2 * m + 1]);
        }
    }
    float xn[32];
    #pragma unroll
    for (int cp = 0; cp < 16; cp++) {
        xn[2 * cp] = lo2(acc[cp]);
        xn[2 * cp + 1] = hi2(acc[cp]);
    }
    #pragma unroll
    for (int c = 0; c < 32; c++) g_xp[c * NPOS + p] = xn[c];
    float rn[32];
    gate_res_p(xn, rn, s_gw, s_gb, s_rw, s_rb);
    #pragma unroll
    for (int c = 0; c < 32; c++) g_rp[c * NPOS + p] = rn[c];

    reduce_stats<256>(s_red, s_p1, s_p2, rn, tid, prt, 0, 0);
}

// ============ warp-pair k-split tf32 MMA layer kernel ============
// block = 128 threads = 4 warps = 2 pairs; pair handles 32 positions;
// within a pair, warp h owns k in [16h, 16h+16) and finalizes position
// tiles nt in {2h, 2h+1}.
__global__ __launch_bounds__(128, 7) void k_layer(
    const float* __restrict__ gate_w, const float* __restrict__ gate_b,
    const float* __restrict__ res_w, const float* __restrict__ res_b,
    const float* __restrict__ bn_g, const float* __restrict__ bn_b,
    int layer)
{
    __shared__ unsigned s_gwh[512], s_gwl[512];     // [j][k] presplit
    __shared__ unsigned s_rwh[1024], s_rwl[1024];   // [c][k] presplit
    __shared__ __align__(16) float sbuf[64 * SBST]; // [pos][ch] then [pos][cm]
    __shared__ float s_xch[128 * 17];               // partial-C exchange
    __shared__ float s_gb[16], s_rb[32];
    __shared__ float s_scale[32], s_shift[32];
    __shared__ float s_st[2][32];

    int tid = threadIdx.x;
    int l = tid & 31;
    int h = (tid >> 5) & 1;
    int pr = tid >> 6;
    int gr = l >> 2, gc = l & 3;
    int prt = blockIdx.x & (NPART - 1);
    int P0 = blockIdx.x * 64;
    int pb = P0 + pr * 32;
    int lrb = pr * 32;
    int kb = 16 * h;

    // stage weights with precomputed tf32 splits
    #pragma unroll
    for (int i = tid; i < 512; i += 128) {
        unsigned hi, lo;
        split_tf32(gate_w[layer * 512 + i], hi, lo);
        s_gwh[i] = hi; s_gwl[i] = lo;
    }
    #pragma unroll
    for (int i = tid; i < 1024; i += 128) {
        unsigned hi, lo;
        split_tf32(res_w[layer * 1024 + i], hi, lo);
        s_rwh[i] = hi; s_rwl[i] = lo;
    }
    if (tid >= 32 && tid < 48) s_gb[tid - 32] = gate_b[layer * 16 + tid - 32];
    if (tid >= 96) s_rb[tid - 96] = res_b[layer * 32 + tid - 96];
    bn_combine32(bn_g + (layer - 1) * 32, bn_b + (layer - 1) * 32, layer - 1,
                 s_scale, s_shift, tid);
    if (tid >= 64 && tid < 128) ((float*)s_st)[tid - 64] = 0.f;
    __syncthreads();

    // ---- phase A: BN + residual; thread = 2 positions x 8 channels ----
    {
        int posq = tid & 31;        // position pair index in block
        int cg = tid >> 5;          // channel group (8 ch)
        int pA = P0 + 2 * posq;
        float va[8], vb[8];
        #pragma unroll
        for (int m = 0; m < 8; m++) {
            int c = 8 * cg + m;
            float2 xv = *(const float2*)&g_xp[(size_t)c * NPOS + pA];
            float2 rv = *(const float2*)&g_rp[(size_t)c * NPOS + pA];
            float sc = s_scale[c], sh = s_shift[c];
            float v0 = fmaf(sc, rv.x, xv.x + sh);
            float v1 = fmaf(sc, rv.y, xv.y + sh);
            *(float2*)&g_xp[(size_t)c * NPOS + pA] = make_float2(v0, v1);
            va[m] = v0; vb[m] = v1;
        }
        float* r0 = sbuf + (2 * posq) * SBST + 8 * cg;
        *(float4*)r0       = make_float4(va[0], va[1], va[2], va[3]);
        *(float4*)(r0 + 4) = make_float4(va[4], va[5], va[6], va[7]);
        float* r1 = r0 + SBST;
        *(float4*)r1       = make_float4(vb[0], vb[1], vb[2], vb[3]);
        *(float4*)(r1 + 4) = make_float4(vb[4], vb[5], vb[6], vb[7]);
    }
    __syncthreads();

    // ---- gate partial GEMM: m16 n32 k16 (my k half) ----
    float gC[4][4];
    #pragma unroll
    for (int nt = 0; nt < 4; nt++) {
        float b0 = h ? 0.f : s_gb[gr];
        float b1 = h ? 0.f : s_gb[gr + 8];
        gC[nt][0] = gC[nt][1] = b0;
        gC[nt][2] = gC[nt][3] = b1;
    }
    #pragma unroll
    for (int kt = 0; kt < 2; kt++) {
        int ab = gr * 32 + kb + kt * 8 + gc;
        unsigned ah[4], al[4];
        ah[0] = s_gwh[ab];       al[0] = s_gwl[ab];
        ah[1] = s_gwh[ab + 256]; al[1] = s_gwl[ab + 256];
        ah[2] = s_gwh[ab + 4];   al[2] = s_gwl[ab + 4];
        ah[3] = s_gwh[ab + 260]; al[3] = s_gwl[ab + 260];
        #pragma unroll
        for (int nt = 0; nt < 4; nt++) {
            int row = (lrb + nt * 8 + gr) * SBST + kb + kt * 8 + gc;
            float b0f = sbuf[row], b1f = sbuf[row + 4];
            unsigned b0h, b0l, b1h, b1l;
            split_tf32(b0f, b0h, b0l);
            split_tf32(b1f, b1h, b1l);
            mma_tf32(gC[nt], ah, b0h, b1h);
            mma_tf32(gC[nt], ah, b0l, b1l);
            mma_tf32(gC[nt], al, b0h, b1h);
        }
    }

    // exchange gate partials for partner's tiles; combine mine
    #pragma unroll
    for (int j = 0; j < 2; j++) {
        int ntp = 2 * (1 - h) + j;
        #pragma unroll
        for (int e = 0; e < 4; e++) s_xch[tid * 17 + j * 4 + e] = gC[ntp][e];
    }
    __syncthreads();
    int ptid = tid ^ 32;
    #pragma unroll
    for (int j = 0; j < 2; j++) {
        int nt = 2 * h + j;
        #pragma unroll
        for (int e = 0; e < 4; e++) gC[nt][e] += s_xch[ptid * 17 + j * 4 + e];
    }
    // concat-mish for my position tiles -> sbuf[pos][cm]
    #pragma unroll
    for (int j = 0; j < 2; j++) {
        int nt = 2 * h + j;
        int r0 = (lrb + nt * 8 + 2 * gc) * SBST;
        int r1 = r0 + SBST;
        float mp, mn;
        mish_pair(gC[nt][0], mp, mn); sbuf[r0 + gr] = mp;      sbuf[r0 + gr + 16] = mn;
        mish_pair(gC[nt][1], mp, mn); sbuf[r1 + gr] = mp;      sbuf[r1 + gr + 16] = mn;
        mish_pair(gC[nt][2], mp, mn); sbuf[r0 + gr + 8] = mp;  sbuf[r0 + gr + 24] = mn;
        mish_pair(gC[nt][3], mp, mn); sbuf[r1 + gr + 8] = mp;  sbuf[r1 + gr + 24] = mn;
    }
    __syncthreads();

    // ---- res partial GEMM: m32 n32 k16 (my cm half) ----
    float rC[2][4][4];
    #pragma unroll
    for (int mt = 0; mt < 2; mt++)
        #pragma unroll
        for (int nt = 0; nt < 4; nt++) {
            float b0 = h ? 0.f : s_rb[16 * mt + gr];
            float b1 = h ? 0.f : s_rb[16 * mt + gr + 8];
            rC[mt][nt][0] = rC[mt][nt][1] = b0;
            rC[mt][nt][2] = rC[mt][nt][3] = b1;
        }
    #pragma unroll
    for (int kt = 0; kt < 2; kt++) {
        int rb0 = gr * 32 + kb + kt * 8 + gc;
        int rb1 = rb0 + 512;   // (16+gr)*32 offset
        unsigned ah0[4], al0[4], ah1[4], al1[4];
        ah0[0] = s_rwh[rb0];       al0[0] = s_rwl[rb0];
        ah0[1] = s_rwh[rb0 + 256]; al0[1] = s_rwl[rb0 + 256];
        ah0[2] = s_rwh[rb0 + 4];   al0[2] = s_rwl[rb0 + 4];
        ah0[3] = s_rwh[rb0 + 260]; al0[3] = s_rwl[rb0 + 260];
        ah1[0] = s_rwh[rb1];       al1[0] = s_rwl[rb1];
        ah1[1] = s_rwh[rb1 + 256]; al1[1] = s_rwl[rb1 + 256];
        ah1[2] = s_rwh[rb1 + 4];   al1[2] = s_rwl[rb1 + 4];
        ah1[3] = s_rwh[rb1 + 260]; al1[3] = s_rwl[rb1 + 260];
        #pragma unroll
        for (int nt = 0; nt < 4; nt++) {
            int row = (lrb + nt * 8 + gr) * SBST + kb + kt * 8 + gc;
            float b0f = sbuf[row], b1f = sbuf[row + 4];
            unsigned b0h, b0l, b1h, b1l;
            split_tf32(b0f, b0h, b0l);
            split_tf32(b1f, b1h, b1l);
            mma_tf32(rC[0][nt], ah0, b0h, b1h);
            mma_tf32(rC[0][nt], ah0, b0l, b1l);
            mma_tf32(rC[0][nt], al0, b0h, b1h);
            mma_tf32(rC[1][nt], ah1, b0h, b1h);
            mma_tf32(rC[1][nt], ah1, b0l, b1l);
            mma_tf32(rC[1][nt], al1, b0h, b1h);
        }
    }

    // exchange res partials; combine mine
    #pragma unroll
    for (int mt = 0; mt < 2; mt++)
        #pragma unroll
        for (int j = 0; j < 2; j++) {
            int ntp = 2 * (1 - h) + j;
            #pragma unroll
            for (int e = 0; e < 4; e++)
                s_xch[tid * 17 + mt * 8 + j * 4 + e] = rC[mt][ntp][e];
        }
    __syncthreads();
    #pragma unroll
    for (int mt = 0; mt < 2; mt++)
        #pragma unroll
        for (int j = 0; j < 2; j++) {
            int nt = 2 * h + j;
            #pragma unroll
            for (int e = 0; e < 4; e++)
                rC[mt][nt][e] += s_xch[ptid * 17 + mt * 8 + j * 4 + e];
        }

    // ---- store r + stats for my position tiles ----
    float s4[4] = {0.f, 0.f, 0.f, 0.f}, q4[4] = {0.f, 0.f, 0.f, 0.f};
    #pragma unroll
    for (int mt = 0; mt < 2; mt++)
        #pragma unroll
        for (int j = 0; j < 2; j++) {
            int nt = 2 * h + j;
            int pcol = nt * 8 + 2 * gc;
            float a0 = rC[mt][nt][0], a1 = rC[mt][nt][1];
            float a2 = rC[mt][nt][2], a3 = rC[mt][nt][3];
            *(float2*)&g_rp[(size_t)(16 * mt + gr) * NPOS + pb + pcol] =
                make_float2(a0, a1);
            *(float2*)&g_rp[(size_t)(16 * mt + gr + 8) * NPOS + pb + pcol] =
                make_float2(a2, a3);
            s4[2 * mt]     += a0 + a1;
            q4[2 * mt]      = fmaf(a0, a0, fmaf(a1, a1, q4[2 * mt]));
            s4[2 * mt + 1] += a2 + a3;
            q4[2 * mt + 1]  = fmaf(a2, a2, fmaf(a3, a3, q4[2 * mt + 1]));
        }
    #pragma unroll
    for (int d = 1; d < 4; d <<= 1) {
        #pragma unroll
        for (int i = 0; i < 4; i++) {
            s4[i] += __shfl_xor_sync(0xffffffffu, s4[i], d);
            q4[i] += __shfl_xor_sync(0xffffffffu, q4[i], d);
        }
    }
    if (gc == 0) {
        #pragma unroll
        for (int i = 0; i < 4; i++) {
            atomicAdd(&s_st[0][8 * i + gr], s4[i]);
            atomicAdd(&s_st[1][8 * i + gr], q4[i]);
        }
    }
    __syncthreads();
    if (tid < 64) {
        int c = tid & 31, kind = tid >> 5;
        atomicAdd(stat_ptr(prt, layer, kind) + c, s_st[kind][c]);
    }
}

// apply BN(39) + residual -> final x into g_xf; stats[40]
__global__ __launch_bounds__(64, 7) void k_endA(
    const float* __restrict__ bn_g, const float* __restrict__ bn_b)
{
    __shared__ __align__(16) float4 s_red4[8 * 65];
    __shared__ __align__(16) float4 s_ps[64], s_pq[64];
    __shared__ float s_scale[32], s_shift[32];
    int tid = threadIdx.x;
    int p = blockIdx.x * 64 + tid;
    int prt = blockIdx.x & (NPART - 1);
    bn_combine32(bn_g + 39 * 32, bn_b + 39 * 32, 39, s_scale, s_shift, tid);
    __syncthreads();
    float xn[32];
    #pragma unroll
    for (int c = 0; c < 32; c++)
        xn[c] = fmaf(s_scale[c], g_rp[(size_t)c * NPOS + p],
                     g_xp[(size_t)c * NPOS + p] + s_shift[c]);
    #pragma unroll
    for (int cq = 0; cq < 8; cq++)
        g_xf[cq * NPOS + p] = make_float4(xn[4 * cq], xn[4 * cq + 1],
                                          xn[4 * cq + 2], xn[4 * cq + 3]);
    reduce64(s_red4, s_ps, s_pq, xn, tid, prt, 40);
}

// tiled end_conv1: z[128] = W1 @ concat_mish(bn1(x)); stats[41]
__global__ __launch_bounds__(256, 3) void k_endB(
    const float* __restrict__ bn1_g, const float* __restrict__ bn1_b,
    const float* __restrict__ w1, const float* __restrict__ b1)
{
    __shared__ __align__(16) float s_w[128 * 68];
    __shared__ __align__(16) float s_y[64 * 68];
    __shared__ float s_ps[128 * 17], s_pq[128 * 17];
    __shared__ float s_scale[32], s_shift[32];

    int tid = threadIdx.x;
    int p0 = blockIdx.x * 64;
    int prt = blockIdx.x & (NPART - 1);

    bn_combine32(bn1_g, bn1_b, 40, s_scale, s_shift, tid);

    #pragma unroll
    for (int i = tid * 4; i < 8192; i += 1024) {
        float4 v = *(const float4*)(w1 + i);
        int o = i >> 6, k = i & 63;
        *(float4*)&s_w[o * 68 + k] = v;
    }
    __syncthreads();

    #pragma unroll
    for (int it = 0; it < 2; it++) {
        int cq = (tid >> 6) + it * 4;
        int pos = tid & 63;
        float4 xq = g_xf[cq * NPOS + p0 + pos];
        float xv[4] = {xq.x, xq.y, xq.z, xq.w};
        #pragma unroll
        for (int u = 0; u < 4; u++) {
            int c = cq * 4 + u;
            float t = fmaf(s_scale[c], xv[u], s_shift[c]);
            float yp, yn;
            mish_pair(t, yp, yn);
            s_y[c * 68 + pos]        = yp;
            s_y[(c + 32) * 68 + pos] = yn;
        }
    }
    __syncthreads();

    int ty = tid >> 4;
    int tx = tid & 15;
    int o0 = ty * 8;
    u64 acc[8][2];
    #pragma unroll
    for (int i = 0; i < 8; i++) {
        u64 b = pack2(__ldg(b1 + o0 + i));
        acc[i][0] = b; acc[i][1] = b;
    }
    #pragma unroll 8
    for (int k = 0; k < 64; k++) {
        ulonglong2 yv = *(const ulonglong2*)&s_y[k * 68 + tx * 4];
        #pragma unroll
        for (int i = 0; i < 8; i++) {
            u64 w = pack2(s_w[(o0 + i) * 68 + k]);
            fma2(acc[i][0], w, yv.x, acc[i][0]);
            fma2(acc[i][1], w, yv.y, acc[i][1]);
        }
    }
    #pragma unroll
    for (int i = 0; i < 8; i++) {
        float a0 = lo2(acc[i][0]), a1 = hi2(acc[i][0]);
        float a2 = lo2(acc[i][1]), a3 = hi2(acc[i][1]);
        *(float4*)&g_z[(size_t)(o0 + i) * NPOS + p0 + tx * 4] =
            make_float4(a0, a1, a2, a3);
        s_ps[(o0 + i) * 17 + tx] = a0 + a1 + a2 + a3;
        s_pq[(o0 + i) * 17 + tx] =
            fmaf(a0, a0, fmaf(a1, a1, fmaf(a2, a2, a3 * a3)));
    }
    __syncthreads();
    {
        int o = tid & 127, kind = tid >> 7;
        const float* src = kind ? s_pq : s_ps;
        float t = 0.f;
        #pragma unroll
        for (int j = 0; j < 16; j++) t += src[o * 17 + j];
        atomicAdd(stat_ptr(prt, 41, kind) + o, t);
    }
}

// out = end_conv2 (256x256) @ concat_mish(bn2(z)); f32x2 packed FMA.
__global__ __launch_bounds__(256) void k_endC(
    const float* __restrict__ bn2_g, const float* __restrict__ bn2_b,
    const float* __restrict__ w2, const float* __restrict__ b2,
    float* __restrict__ out)
{
    __shared__ __align__(16) float sBuf[256 * 33 + 32 * 64];
    __shared__ float sSc[128], sSh[128], sB2[256];
    float* sW = sBuf;
    float* sV = sBuf + 256 * 33;

    int tid = threadIdx.x;
    int ty = tid >> 3;
    int tx = tid & 7;
    int p0 = blockIdx.x * 64;
    int l0 = p0 >> 3;

    if (tid < 128) {
        float s = 0.f, q = 0.f;
        #pragma unroll
        for (int pp = 0; pp < NPART; pp++) {
            s += g_statp[pp][41][0][tid];
            q += g_statp[pp][41][1][tid];
        }
        float m = s * (1.0f / NPOSf);
        float var = q * (1.0f / NPOSf) - m * m;
        float inv = rsqrtf(var + 1e-5f);
        float sc = bn2_g[tid] * inv;
        sSc[tid] = sc;
        sSh[tid] = bn2_b[tid] - m * sc;
    }
    sB2[tid] = b2[tid];

    u64 acc[8][4];
    #pragma unroll
    for (int i = 0; i < 8; i++)
        #pragma unroll
        for (int jp = 0; jp < 4; jp++) acc[i][jp] = 0ULL;

    for (int kc = 0; kc < 8; kc++) {
        __syncthreads();
        for (int idx = tid; idx < 8192; idx += 256) {
            int o = idx >> 5, k = idx & 31;
            sW[o * 33 + k] = w2[o * 256 + kc * 32 + k];
        }
        for (int idx = tid; idx < 2048; idx += 256) {
            int kk = idx >> 6, qq = idx & 63;
            int c = kc * 32 + kk;
            int zc = (c < 128) ? c : c - 128;
            float t = fmaf(sSc[zc], g_z[zc * NPOS + p0 + qq], sSh[zc]);
            sV[kk * 64 + qq] = mishf((c < 128) ? t : -t);
        }
        __syncthreads();
        int woff = ty * 8 * 33;
        int voff = tx * 8;
        #pragma unroll
        for (int k = 0; k < 32; k++) {
            u64 vv[4];
            #pragma unroll
            for (int jp = 0; jp < 4; jp++)
                vv[jp] = *(const u64*)&sV[k * 64 + voff + jp * 2];
            #pragma unroll
            for (int i = 0; i < 8; i++) {
                u64 wd = pack2(sW[woff + i * 33 + k]);
                #pragma unroll
                for (int jp = 0; jp < 4; jp++)
                    fma2(acc[i][jp], wd, vv[jp], acc[i][jp]);
            }
        }
    }

    for (int oh = 0; oh < 2; oh++) {
        __syncthreads();
        if ((ty >> 4) == oh) {
            int orow = (ty & 15) * 8;
            #pragma unroll
            for (int i = 0; i < 8; i++) {
                float bias = sB2[oh * 128 + orow + i];
                #pragma unroll
                for (int j = 0; j < 8; j++) {
                    int jp = j >> 1;
                    float f = (j & 1) ? hi2(acc[i][jp]) : lo2(acc[i][jp]);
                    sBuf[(orow + i) * 64 + j * 8 + tx] = f + bias;
                }
            }
        }
        __syncthreads();
        for (int idx = tid; idx < 2048; idx += 256) {
            int oloc = idx >> 4;
            int b = (idx >> 1) & 7;
            int hh = idx & 1;
            float4 v = *(float4*)&sBuf[oloc * 64 + b * 8 + hh * 4];
            *(float4*)&out[(size_t)b * 2097152 + (size_t)(oh * 128 + oloc) * 8192
                           + l0 + hh * 4] = v;
        }
    }
}

extern "C" void kernel_launch(void* const* d_in, const int* in_sizes, int n_in,
                              void* d_out, int out_size) {
    const float* x           = (const float*)d_in[0];
    const float* start_w     = (const float*)d_in[1];
    const float* start_b     = (const float*)d_in[2];
    const float* gate_w      = (const float*)d_in[3];
    const float* gate_b      = (const float*)d_in[4];
    const float* res_w       = (const float*)d_in[5];
    const float* res_b       = (const float*)d_in[6];
    const float* bn_g        = (const float*)d_in[7];
    const float* bn_b        = (const float*)d_in[8];
    const float* end_bn1_g   = (const float*)d_in[9];
    const float* end_bn1_b   = (const float*)d_in[10];
    const float* end_conv1_w = (const float*)d_in[11];
    const float* end_conv1_b = (const float*)d_in[12];
    const float* end_bn2_g   = (const float*)d_in[13];
    const float* end_bn2_b   = (const float*)d_in[14];
    const float* end_conv2_w = (const float*)d_in[15];
    const float* end_conv2_b = (const float*)d_in[16];
    float* out = (float*)d_out;

    k_prep<<<336, 512>>>();
    k_start<<<256, 256>>>(x, start_w, start_b, gate_w, gate_b, res_w, res_b);
    for (int i = 1; i < 40; i++)
        k_layer<<<1024, 128>>>(gate_w, gate_b, res_w, res_b, bn_g, bn_b, i);
    k_endA<<<1024, 64>>>(bn_g, bn_b);
    k_endB<<<1024, 256>>>(end_bn1_g, end_bn1_b, end_conv1_w, end_conv1_b);
    k_endC<<<1024, 256>>>(end_bn2_g, end_bn2_b, end_conv2_w, end_conv2_b, out);
}

// round 15
// speedup vs baseline: 1.1498x; 1.1498x over previous
#include <cuda_runtime.h>

typedef unsigned long long u64;
#define NPOS 65536
#define NPOSf 65536.0f
#define NPART 16
#define SBST 36

// persistent scratch (device globals)
__device__ float2 g_x2[16 * NPOS];              // residual stream x, ch-paired
__device__ float  g_rp[32 * NPOS];              // pre-BN layer output r, plain [ch][pos]
__device__ float4 g_xf[8 * NPOS];               // final x, channel quads
__device__ float  g_z[128 * NPOS];              // end_conv1 output
__device__ float  g_statp[NPART][42][2][128];   // partitioned stats

__device__ __forceinline__ float* stat_ptr(int part, int op, int kind) {
    return &g_statp[part][op][kind][0];
}

// ---- PDL helpers (no-ops if PDL not honored) ----
__device__ __forceinline__ void pdl_trigger() {
#if defined(__CUDA_ARCH__) && __CUDA_ARCH__ >= 900
    cudaTriggerProgrammaticLaunchCompletion();
#endif
}
__device__ __forceinline__ void pdl_wait() {
#if defined(__CUDA_ARCH__) && __CUDA_ARCH__ >= 900
    cudaGridDependencySynchronize();
#endif
}

__device__ __forceinline__ void fma2(u64 &d, u64 a, u64 b, u64 c) {
    asm("fma.rn.f32x2 %0, %1, %2, %3;" : "=l"(d) : "l"(a), "l"(b), "l"(c));
}
__device__ __forceinline__ u64 pack2(float f) {
    u64 r; unsigned b = __float_as_uint(f);
    asm("mov.b64 %0, {%1, %1};" : "=l"(r) : "r"(b));
    return r;
}
__device__ __forceinline__ float lo2(u64 v) { return __uint_as_float((unsigned)v); }
__device__ __forceinline__ float hi2(u64 v) { return __uint_as_float((unsigned)(v >> 32)); }

__device__ __forceinline__ float mishf(float v) {
    float u = __expf(fminf(fmaxf(v, -20.0f), 20.0f));
    float w = fmaf(u, u, u + u);
    return v * __fdividef(w, w + 2.0f);
}

// mish(a) and mish(-a) sharing one exp
__device__ __forceinline__ void mish_pair(float a, float &mp, float &mn) {
    float ac = fminf(fmaxf(a, -20.0f), 20.0f);
    float u = __expf(ac);
    float A = fmaf(u, u, u + u);
    mp = a * __fdividef(A, A + 2.0f);
    float B = fmaf(2.0f, u, 1.0f);
    mn = -a * __fdividef(B, fmaf(u + u, u, B));
}

// ---- tf32 helpers ----
__device__ __forceinline__ unsigned cvt_tf32(float f) {
    unsigned r; asm("cvt.rna.tf32.f32 %0, %1;" : "=r"(r) : "f"(f)); return r;
}
__device__ __forceinline__ void split_tf32(float f, unsigned &hi, unsigned &lo) {
    hi = cvt_tf32(f);
    lo = cvt_tf32(f - __uint_as_float(hi));
}
__device__ __forceinline__ void mma_tf32(float* c, const unsigned* a,
                                         unsigned b0, unsigned b1) {
    asm("mma.sync.aligned.m16n8k8.row.col.f32.tf32.tf32.f32 "
        "{%0,%1,%2,%3}, {%4,%5,%6,%7}, {%8,%9}, {%0,%1,%2,%3};"
        : "+f"(c[0]), "+f"(c[1]), "+f"(c[2]), "+f"(c[3])
        : "r"(a[0]), "r"(a[1]), "r"(a[2]), "r"(a[3]), "r"(b0), "r"(b1));
}

// legacy reduction (k_start, 256 threads)
template<int BS>
__device__ __forceinline__ void reduce_stats(float* red, float* part1, float* part2,
                                             const float* vals, int tid,
                                             int prt, int op, int coff) {
    __syncthreads();
    #pragma unroll
    for (int c = 0; c < 32; c++) red[tid * 34 + c] = vals[c];
    __syncthreads();
    {
        int c = tid & 31, seg = tid >> 5;
        int base = seg * 32;
        float s = 0.f, q = 0.f;
        #pragma unroll
        for (int r = 0; r < 32; r++) {
            float v = red[(base + r) * 34 + c];
            s += v;
            q = fmaf(v, v, q);
        }
        part1[seg * 32 + c] = s;
        part2[seg * 32 + c] = q;
    }
    __syncthreads();
    if (tid < 64) {
        int c = tid & 31, kind = tid >> 5;
        const float* pp = kind ? part2 : part1;
        float t = 0.f;
        #pragma unroll
        for (int sg = 0; sg < BS / 32; sg++) t += pp[sg * 32 + c];
        atomicAdd(stat_ptr(prt, op, kind) + coff + c, t);
    }
}

// float4-vectorized reduction for 64-thread blocks; vals[32] per thread.
__device__ __forceinline__ void reduce64(float4* red4, float4* ps, float4* pq,
                                         const float* vals, int tid,
                                         int prt, int op) {
    __syncthreads();
    #pragma unroll
    for (int q = 0; q < 8; q++)
        red4[q * 65 + tid] = make_float4(vals[4 * q], vals[4 * q + 1],
                                         vals[4 * q + 2], vals[4 * q + 3]);
    __syncthreads();
    {
        int q = tid & 7, seg = tid >> 3;
        float4 s = make_float4(0.f, 0.f, 0.f, 0.f);
        float4 sq = make_float4(0.f, 0.f, 0.f, 0.f);
        #pragma unroll
        for (int r = 0; r < 8; r++) {
            float4 v = red4[q * 65 + seg * 8 + r];
            s.x += v.x; s.y += v.y; s.z += v.z; s.w += v.w;
            sq.x = fmaf(v.x, v.x, sq.x);
            sq.y = fmaf(v.y, v.y, sq.y);
            sq.z = fmaf(v.z, v.z, sq.z);
            sq.w = fmaf(v.w, v.w, sq.w);
        }
        ps[seg * 8 + q] = s;
        pq[seg * 8 + q] = sq;
    }
    __syncthreads();
    {
        int c = tid & 31, kind = tid >> 5;
        int quad = c >> 2, comp = c & 3;
        const float* base = (const float*)(kind ? pq : ps);
        float t = 0.f;
        #pragma unroll
        for (int seg = 0; seg < 8; seg++)
            t += base[(seg * 8 + quad) * 4 + comp];
        atomicAdd(stat_ptr(prt, op, kind) + c, t);
    }
}

// combine partitioned stats -> BN scale/shift (threads 0..31)
__device__ __forceinline__ void bn_combine32(const float* g, const float* b, int op,
                                             float* s_scale, float* s_shift, int tid) {
    if (tid < 32) {
        float s = 0.f, q = 0.f;
        #pragma unroll
        for (int pp = 0; pp < NPART; pp++) {
            s += g_statp[pp][op][0][tid];
            q += g_statp[pp][op][1][tid];
        }
        float m = s * (1.0f / NPOSf);
        float var = q * (1.0f / NPOSf) - m * m;
        float inv = rsqrtf(var + 1e-5f);
        float sc = g[tid] * inv;
        s_scale[tid] = sc;
        s_shift[tid] = b[tid] - m * sc;
    }
}

// full-width paired gate(16x32)->concat-mish->res(32x32) (k_start only)
__device__ __forceinline__ void gate_res_p(const float* xn, float* rn,
                                           const float* s_gw, const float* s_gb,
                                           const float* s_rw, const float* s_rb) {
    u64 accg[8];
    #pragma unroll
    for (int jp = 0; jp < 8; jp++) accg[jp] = *(const u64*)&s_gb[2 * jp];
    const ulonglong2* gw2 = (const ulonglong2*)s_gw;
    #pragma unroll
    for (int k = 0; k < 32; k++) {
        u64 xk = pack2(xn[k]);
        #pragma unroll
        for (int m = 0; m < 4; m++) {
            ulonglong2 w = gw2[k * 4 + m];
            fma2(accg[2 * m],     w.x, xk, accg[2 * m]);
            fma2(accg[2 * m + 1], w.y, xk, accg[2 * m + 1]);
        }
    }
    float cm[32];
    #pragma unroll
    for (int jp = 0; jp < 8; jp++) {
        float a0 = lo2(accg[jp]), a1 = hi2(accg[jp]);
        mish_pair(a0, cm[2 * jp],     cm[2 * jp + 16]);
        mish_pair(a1, cm[2 * jp + 1], cm[2 * jp + 17]);
    }
    u64 accr[16];
    #pragma unroll
    for (int cp = 0; cp < 16; cp++) accr[cp] = *(const u64*)&s_rb[2 * cp];
    const ulonglong2* rw2 = (const ulonglong2*)s_rw;
    #pragma unroll
    for (int k = 0; k < 32; k++) {
        u64 ck = pack2(cm[k]);
        #pragma unroll
        for (int m = 0; m < 8; m++) {
            ulonglong2 w = rw2[k * 8 + m];
            fma2(accr[2 * m],     w.x, ck, accr[2 * m]);
            fma2(accr[2 * m + 1], w.y, ck, accr[2 * m + 1]);
        }
    }
    #pragma unroll
    for (int cp = 0; cp < 16; cp++) {
        rn[2 * cp]     = lo2(accr[cp]);
        rn[2 * cp + 1] = hi2(accr[cp]);
    }
}

__global__ void k_prep() {
    int idx = blockIdx.x * 512 + threadIdx.x;
    float* st = &g_statp[0][0][0][0];
    if (idx < NPART * 42 * 2 * 128) st[idx] = 0.f;
}

// start conv (32x256) + layer-0 gate/res + stats[0]
__global__ __launch_bounds__(256, 2) void k_start(
    const float* __restrict__ xin,
    const float* __restrict__ start_w, const float* __restrict__ start_b,
    const float* __restrict__ gate_w, const float* __restrict__ gate_b,
    const float* __restrict__ res_w, const float* __restrict__ res_b)
{
    __shared__ __align__(16) float s_red[256 * 34];
    __shared__ float s_p1[256], s_p2[256];
    __shared__ __align__(16) float s_gw[512];
    __shared__ __align__(16) float s_rw[1024];
    __shared__ __align__(8) float s_gb[16];
    __shared__ __align__(8) float s_rb[32];
    __shared__ __align__(8) float s_sb[32];

    int tid = threadIdx.x;
    int p = blockIdx.x * 256 + tid;
    int prt = blockIdx.x & (NPART - 1);

    pdl_trigger();

    for (int idx = tid; idx < 8192; idx += 256) {
        int k = idx >> 5, c = idx & 31;
        s_red[k * 32 + c] = start_w[c * 256 + k];
    }
    for (int i = tid; i < 512; i += 256)  { int j = i & 15, k = i >> 4; s_gw[i] = gate_w[j * 32 + k]; }
    for (int i = tid; i < 1024; i += 256) { int c = i & 31, k = i >> 5; s_rw[i] = res_w[c * 32 + k]; }
    if (tid < 16) s_gb[tid] = gate_b[tid];
    if (tid >= 32 && tid < 64) s_rb[tid - 32] = res_b[tid - 32];
    if (tid >= 64 && tid < 96) s_sb[tid - 64] = start_b[tid - 64];
    pdl_wait();            // k_prep must have zeroed g_statp before our atomics
    __syncthreads();

    u64 acc[16];
    #pragma unroll
    for (int cp = 0; cp < 16; cp++) acc[cp] = *(const u64*)&s_sb[2 * cp];
    const float* xp = xin + (size_t)(p & 7) * (256 * 8192) + (p >> 3);
    const ulonglong2* swT2 = (const ulonglong2*)s_red;
    #pragma unroll 4
    for (int k = 0; k < 256; k++) {
        u64 xk = pack2(xp[k * 8192]);
        #pragma unroll
        for (int m = 0; m < 8; m++) {
            ulonglong2 w = swT2[k * 8 + m];
            fma2(acc[2 * m],     w.x, xk, acc[2 * m]);
            fma2(acc[2 * m + 1], w.y, xk, acc[2 * m + 1]);
        }
    }
    float xn[32];
    #pragma unroll
    for (int cp = 0; cp < 16; cp++) {
        xn[2 * cp] = lo2(acc[cp]);
        xn[2 * cp + 1] = hi2(acc[cp]);
        g_x2[cp * NPOS + p] = make_float2(xn[2 * cp], xn[2 * cp + 1]);
    }
    float rn[32];
    gate_res_p(xn, rn, s_gw, s_gb, s_rw, s_rb);
    #pragma unroll
    for (int c = 0; c < 32; c++) g_rp[c * NPOS + p] = rn[c];

    reduce_stats<256>(s_red, s_p1, s_p2, rn, tid, prt, 0, 0);
}

// ============ tf32 MMA layer kernel (R12 body + PDL prologue overlap) ============
// block = 64 threads = 2 warps; warp handles 32 positions.
__global__ __launch_bounds__(64, 7) void k_layer(
    const float* __restrict__ gate_w, const float* __restrict__ gate_b,
    const float* __restrict__ res_w, const float* __restrict__ res_b,
    const float* __restrict__ bn_g, const float* __restrict__ bn_b,
    int layer)
{
    __shared__ __align__(16) float sbuf[64 * SBST];   // [pos][ch] then [pos][cm]
    __shared__ __align__(16) float s_gw[512];         // [j][k]
    __shared__ __align__(16) float s_rw[1024];        // [c][k]
    __shared__ float s_gb[16], s_rb[32];
    __shared__ float s_scale[32], s_shift[32];
    __shared__ float s_st[2][32];

    int tid = threadIdx.x;
    int w = tid >> 5, l = tid & 31;
    int gr = l >> 2, gc = l & 3;
    int prt = blockIdx.x & (NPART - 1);
    int lp = 32 * w + l;
    int p = blockIdx.x * 64 + lp;
    int pb = blockIdx.x * 64 + 32 * w;   // warp position base

    pdl_trigger();

    // stage weights (independent of previous layer's output -> overlaps via PDL)
    #pragma unroll
    for (int i = tid; i < 128; i += 64)
        *(float4*)&s_gw[4 * i] = *(const float4*)&gate_w[layer * 512 + 4 * i];
    #pragma unroll
    for (int i = tid; i < 256; i += 64)
        *(float4*)&s_rw[4 * i] = *(const float4*)&res_w[layer * 1024 + 4 * i];
    if (tid < 16) s_gb[tid] = gate_b[layer * 16 + tid];
    if (tid >= 32) s_rb[tid - 32] = res_b[layer * 32 + tid - 32];
    if (tid < 32) { s_st[0][tid] = 0.f; s_st[1][tid] = 0.f; }

    pdl_wait();   // previous layer's stats + g_x2/g_rp must be complete

    bn_combine32(bn_g + (layer - 1) * 32, bn_b + (layer - 1) * 32, layer - 1,
                 s_scale, s_shift, tid);
    __syncthreads();

    // ---- phase A: BN + residual; x' -> gmem and sbuf[pos][ch] ----
    float xn[32];
    #pragma unroll
    for (int m = 0; m < 16; m++) {
        float2 xv = g_x2[m * NPOS + p];
        float r0 = g_rp[(2 * m) * NPOS + p];
        float r1 = g_rp[(2 * m + 1) * NPOS + p];
        float v0 = fmaf(s_scale[2 * m],     r0, xv.x + s_shift[2 * m]);
        float v1 = fmaf(s_scale[2 * m + 1], r1, xv.y + s_shift[2 * m + 1]);
        xn[2 * m] = v0; xn[2 * m + 1] = v1;
        g_x2[m * NPOS + p] = make_float2(v0, v1);
    }
    #pragma unroll
    for (int qd = 0; qd < 8; qd++)
        *(float4*)&sbuf[lp * SBST + 4 * qd] =
            make_float4(xn[4 * qd], xn[4 * qd + 1], xn[4 * qd + 2], xn[4 * qd + 3]);
    __syncwarp();

    // ---- gate A fragments (tf32 split) ----
    unsigned gah[4][4], gal[4][4];
    #pragma unroll
    for (int kt = 0; kt < 4; kt++) {
        split_tf32(s_gw[gr * 32 + kt * 8 + gc],           gah[kt][0], gal[kt][0]);
        split_tf32(s_gw[(gr + 8) * 32 + kt * 8 + gc],     gah[kt][1], gal[kt][1]);
        split_tf32(s_gw[gr * 32 + kt * 8 + gc + 4],       gah[kt][2], gal[kt][2]);
        split_tf32(s_gw[(gr + 8) * 32 + kt * 8 + gc + 4], gah[kt][3], gal[kt][3]);
    }

    // ---- gate GEMM m16 n32 k32 ----
    float gC[4][4];
    #pragma unroll
    for (int nt = 0; nt < 4; nt++) {
        gC[nt][0] = gC[nt][1] = s_gb[gr];
        gC[nt][2] = gC[nt][3] = s_gb[gr + 8];
    }
    #pragma unroll
    for (int nt = 0; nt < 4; nt++) {
        int row = (32 * w + nt * 8 + gr) * SBST;
        #pragma unroll
        for (int kt = 0; kt < 4; kt++) {
            float b0f = sbuf[row + kt * 8 + gc];
            float b1f = sbuf[row + kt * 8 + gc + 4];
            unsigned b0h, b0l, b1h, b1l;
            split_tf32(b0f, b0h, b0l);
            split_tf32(b1f, b1h, b1l);
            mma_tf32(gC[nt], gah[kt], b0h, b1h);
            mma_tf32(gC[nt], gah[kt], b0l, b1l);
            mma_tf32(gC[nt], gal[kt], b0h, b1h);
        }
    }
    __syncwarp();   // all gate B reads done before cm overwrites sbuf

    // ---- concat-mish -> sbuf[pos][cm] ----
    #pragma unroll
    for (int nt = 0; nt < 4; nt++) {
        int r0 = (32 * w + nt * 8 + 2 * gc) * SBST;
        int r1 = r0 + SBST;
        float mp, mn;
        mish_pair(gC[nt][0], mp, mn);
        sbuf[r0 + gr] = mp;      sbuf[r0 + gr + 16] = mn;
        mish_pair(gC[nt][1], mp, mn);
        sbuf[r1 + gr] = mp;      sbuf[r1 + gr + 16] = mn;
        mish_pair(gC[nt][2], mp, mn);
        sbuf[r0 + gr + 8] = mp;  sbuf[r0 + gr + 24] = mn;
        mish_pair(gC[nt][3], mp, mn);
        sbuf[r1 + gr + 8] = mp;  sbuf[r1 + gr + 24] = mn;
    }
    __syncwarp();

    // ---- res A fragments ----
    unsigned rah[2][4][4], ral[2][4][4];
    #pragma unroll
    for (int mt = 0; mt < 2; mt++)
        #pragma unroll
        for (int kt = 0; kt < 4; kt++) {
            int rbase = (16 * mt + gr) * 32 + kt * 8 + gc;
            split_tf32(s_rw[rbase],           rah[mt][kt][0], ral[mt][kt][0]);
            split_tf32(s_rw[rbase + 256],     rah[mt][kt][1], ral[mt][kt][1]);
            split_tf32(s_rw[rbase + 4],       rah[mt][kt][2], ral[mt][kt][2]);
            split_tf32(s_rw[rbase + 260],     rah[mt][kt][3], ral[mt][kt][3]);
        }

    // ---- res GEMM m32 n32 k32 ----
    float rC[2][4][4];
    #pragma unroll
    for (int mt = 0; mt < 2; mt++)
        #pragma unroll
        for (int nt = 0; nt < 4; nt++) {
            rC[mt][nt][0] = rC[mt][nt][1] = s_rb[16 * mt + gr];
            rC[mt][nt][2] = rC[mt][nt][3] = s_rb[16 * mt + gr + 8];
        }
    #pragma unroll
    for (int nt = 0; nt < 4; nt++) {
        int row = (32 * w + nt * 8 + gr) * SBST;
        #pragma unroll
        for (int kt = 0; kt < 4; kt++) {
            float b0f = sbuf[row + kt * 8 + gc];
            float b1f = sbuf[row + kt * 8 + gc + 4];
            unsigned b0h, b0l, b1h, b1l;
            split_tf32(b0f, b0h, b0l);
            split_tf32(b1f, b1h, b1l);
            #pragma unroll
            for (int mt = 0; mt < 2; mt++) {
                mma_tf32(rC[mt][nt], rah[mt][kt], b0h, b1h);
                mma_tf32(rC[mt][nt], rah[mt][kt], b0l, b1l);
                mma_tf32(rC[mt][nt], ral[mt][kt], b0h, b1h);
            }
        }
    }

    // ---- store r + per-lane stat partials ----
    float s4[4] = {0.f, 0.f, 0.f, 0.f}, q4[4] = {0.f, 0.f, 0.f, 0.f};
    #pragma unroll
    for (int mt = 0; mt < 2; mt++)
        #pragma unroll
        for (int nt = 0; nt < 4; nt++) {
            int c0r = 16 * mt + gr, c1r = c0r + 8;
            int pcol = nt * 8 + 2 * gc;
            float a0 = rC[mt][nt][0], a1 = rC[mt][nt][1];
            float a2 = rC[mt][nt][2], a3 = rC[mt][nt][3];
            *(float2*)&g_rp[(size_t)c0r * NPOS + pb + pcol] = make_float2(a0, a1);
            *(float2*)&g_rp[(size_t)c1r * NPOS + pb + pcol] = make_float2(a2, a3);
            s4[2 * mt]     += a0 + a1;
            q4[2 * mt]      = fmaf(a0, a0, fmaf(a1, a1, q4[2 * mt]));
            s4[2 * mt + 1] += a2 + a3;
            q4[2 * mt + 1]  = fmaf(a2, a2, fmaf(a3, a3, q4[2 * mt + 1]));
        }
    // quad reduce over gc; lane gc==0 owns channels gr + 8*i
    #pragma unroll
    for (int d = 1; d < 4; d <<= 1) {
        #pragma unroll
        for (int i = 0; i < 4; i++) {
            s4[i] += __shfl_xor_sync(0xffffffffu, s4[i], d);
            q4[i] += __shfl_xor_sync(0xffffffffu, q4[i], d);
        }
    }
    if (gc == 0) {
        #pragma unroll
        for (int i = 0; i < 4; i++) {
            atomicAdd(&s_st[0][gr + 8 * i], s4[i]);
            atomicAdd(&s_st[1][gr + 8 * i], q4[i]);
        }
    }
    __syncthreads();
    if (tid < 64) {
        int c = tid & 31, kind = tid >> 5;
        atomicAdd(stat_ptr(prt, layer, kind) + c, s_st[kind][c]);
    }
}

// apply BN(39) + residual -> final x into g_xf; stats[40]
__global__ __launch_bounds__(64, 7) void k_endA(
    const float* __restrict__ bn_g, const float* __restrict__ bn_b)
{
    __shared__ __align__(16) float4 s_red4[8 * 65];
    __shared__ __align__(16) float4 s_ps[64], s_pq[64];
    __shared__ float s_scale[32], s_shift[32];
    int tid = threadIdx.x;
    int p = blockIdx.x * 64 + tid;
    int prt = blockIdx.x & (NPART - 1);
    pdl_trigger();
    pdl_wait();
    bn_combine32(bn_g + 39 * 32, bn_b + 39 * 32, 39, s_scale, s_shift, tid);
    __syncthreads();
    float xn[32];
    #pragma unroll
    for (int m = 0; m < 16; m++) {
        float2 xv = g_x2[m * NPOS + p];
        float r0 = g_rp[(2 * m) * NPOS + p];
        float r1 = g_rp[(2 * m + 1) * NPOS + p];
        xn[2 * m]     = fmaf(s_scale[2 * m],     r0, xv.x + s_shift[2 * m]);
        xn[2 * m + 1] = fmaf(s_scale[2 * m + 1], r1, xv.y + s_shift[2 * m + 1]);
    }
    #pragma unroll
    for (int cq = 0; cq < 8; cq++)
        g_xf[cq * NPOS + p] = make_float4(xn[4 * cq], xn[4 * cq + 1],
                                          xn[4 * cq + 2], xn[4 * cq + 3]);
    reduce64(s_red4, s_ps, s_pq, xn, tid, prt, 40);
}

// tiled end_conv1: z[128] = W1 @ concat_mish(bn1(x)); stats[41]
__global__ __launch_bounds__(256, 3) void k_endB(
    const float* __restrict__ bn1_g, const float* __restrict__ bn1_b,
    const float* __restrict__ w1, const float* __restrict__ b1)
{
    __shared__ __align__(16) float s_w[128 * 68];
    __shared__ __align__(16) float s_y[64 * 68];
    __shared__ float s_ps[128 * 17], s_pq[128 * 17];
    __shared__ float s_scale[32], s_shift[32];

    int tid = threadIdx.x;
    int p0 = blockIdx.x * 64;
    int prt = blockIdx.x & (NPART - 1);

    pdl_trigger();

    // stage W first (independent of k_endA's output)
    #pragma unroll
    for (int i = tid * 4; i < 8192; i += 1024) {
        float4 v = *(const float4*)(w1 + i);
        int o = i >> 6, k = i & 63;
        *(float4*)&s_w[o * 68 + k] = v;
    }

    pdl_wait();
    bn_combine32(bn1_g, bn1_b, 40, s_scale, s_shift, tid);
    __syncthreads();

    #pragma unroll
    for (int it = 0; it < 2; it++) {
        int cq = (tid >> 6) + it * 4;
        int pos = tid & 63;
        float4 xq = g_xf[cq * NPOS + p0 + pos];
        float xv[4] = {xq.x, xq.y, xq.z, xq.w};
        #pragma unroll
        for (int u = 0; u < 4; u++) {
            int c = cq * 4 + u;
            float t = fmaf(s_scale[c], xv[u], s_shift[c]);
            float yp, yn;
            mish_pair(t, yp, yn);
            s_y[c * 68 + pos]        = yp;
            s_y[(c + 32) * 68 + pos] = yn;
        }
    }
    __syncthreads();

    int ty = tid >> 4;
    int tx = tid & 15;
    int o0 = ty * 8;
    u64 acc[8][2];
    #pragma unroll
    for (int i = 0; i < 8; i++) {
        u64 b = pack2(__ldg(b1 + o0 + i));
        acc[i][0] = b; acc[i][1] = b;
    }
    #pragma unroll 8
    for (int k = 0; k < 64; k++) {
        ulonglong2 yv = *(const ulonglong2*)&s_y[k * 68 + tx * 4];
        #pragma unroll
        for (int i = 0; i < 8; i++) {
            u64 w = pack2(s_w[(o0 + i) * 68 + k]);
            fma2(acc[i][0], w, yv.x, acc[i][0]);
            fma2(acc[i][1], w, yv.y, acc[i][1]);
        }
    }
    #pragma unroll
    for (int i = 0; i < 8; i++) {
        float a0 = lo2(acc[i][0]), a1 = hi2(acc[i][0]);
        float a2 = lo2(acc[i][1]), a3 = hi2(acc[i][1]);
        *(float4*)&g_z[(size_t)(o0 + i) * NPOS + p0 + tx * 4] =
            make_float4(a0, a1, a2, a3);
        s_ps[(o0 + i) * 17 + tx] = a0 + a1 + a2 + a3;
        s_pq[(o0 + i) * 17 + tx] =
            fmaf(a0, a0, fmaf(a1, a1, fmaf(a2, a2, a3 * a3)));
    }
    __syncthreads();
    {
        int o = tid & 127, kind = tid >> 7;
        const float* src = kind ? s_pq : s_ps;
        float t = 0.f;
        #pragma unroll
        for (int j = 0; j < 16; j++) t += src[o * 17 + j];
        atomicAdd(stat_ptr(prt, 41, kind) + o, t);
    }
}

// out = end_conv2 (256x256) @ concat_mish(bn2(z)); f32x2 packed FMA.
__global__ __launch_bounds__(256) void k_endC(
    const float* __restrict__ bn2_g, const float* __restrict__ bn2_b,
    const float* __restrict__ w2, const float* __restrict__ b2,
    float* __restrict__ out)
{
    __shared__ __align__(16) float sBuf[256 * 33 + 32 * 64];
    __shared__ float sSc[128], sSh[128], sB2[256];
    float* sW = sBuf;
    float* sV = sBuf + 256 * 33;

    int tid = threadIdx.x;
    int ty = tid >> 3;
    int tx = tid & 7;
    int p0 = blockIdx.x * 64;
    int l0 = p0 >> 3;

    pdl_trigger();
    sB2[tid] = b2[tid];
    pdl_wait();

    if (tid < 128) {
        float s = 0.f, q = 0.f;
        #pragma unroll
        for (int pp = 0; pp < NPART; pp++) {
            s += g_statp[pp][41][0][tid];
            q += g_statp[pp][41][1][tid];
        }
        float m = s * (1.0f / NPOSf);
        float var = q * (1.0f / NPOSf) - m * m;
        float inv = rsqrtf(var + 1e-5f);
        float sc = bn2_g[tid] * inv;
        sSc[tid] = sc;
        sSh[tid] = bn2_b[tid] - m * sc;
    }

    u64 acc[8][4];
    #pragma unroll
    for (int i = 0; i < 8; i++)
        #pragma unroll
        for (int jp = 0; jp < 4; jp++) acc[i][jp] = 0ULL;

    for (int kc = 0; kc < 8; kc++) {
        __syncthreads();
        for (int idx = tid; idx < 8192; idx += 256) {
            int o = idx >> 5, k = idx & 31;
            sW[o * 33 + k] = w2[o * 256 + kc * 32 + k];
        }
        for (int idx = tid; idx < 2048; idx += 256) {
            int kk = idx >> 6, qq = idx & 63;
            int c = kc * 32 + kk;
            int zc = (c < 128) ? c : c - 128;
            float t = fmaf(sSc[zc], g_z[zc * NPOS + p0 + qq], sSh[zc]);
            sV[kk * 64 + qq] = mishf((c < 128) ? t : -t);
        }
        __syncthreads();
        int woff = ty * 8 * 33;
        int voff = tx * 8;
        #pragma unroll
        for (int k = 0; k < 32; k++) {
            u64 vv[4];
            #pragma unroll
            for (int jp = 0; jp < 4; jp++)
                vv[jp] = *(const u64*)&sV[k * 64 + voff + jp * 2];
            #pragma unroll
            for (int i = 0; i < 8; i++) {
                u64 wd = pack2(sW[woff + i * 33 + k]);
                #pragma unroll
                for (int jp = 0; jp < 4; jp++)
                    fma2(acc[i][jp], wd, vv[jp], acc[i][jp]);
            }
        }
    }

    for (int oh = 0; oh < 2; oh++) {
        __syncthreads();
        if ((ty >> 4) == oh) {
            int orow = (ty & 15) * 8;
            #pragma unroll
            for (int i = 0; i < 8; i++) {
                float bias = sB2[oh * 128 + orow + i];
                #pragma unroll
                for (int j = 0; j < 8; j++) {
                    int jp = j >> 1;
                    float f = (j & 1) ? hi2(acc[i][jp]) : lo2(acc[i][jp]);
                    sBuf[(orow + i) * 64 + j * 8 + tx] = f + bias;
                }
            }
        }
        __syncthreads();
        for (int idx = tid; idx < 2048; idx += 256) {
            int oloc = idx >> 4;
            int b = (idx >> 1) & 7;
            int hh = idx & 1;
            float4 v = *(float4*)&sBuf[oloc * 64 + b * 8 + hh * 4];
            *(float4*)&out[(size_t)b * 2097152 + (size_t)(oh * 128 + oloc) * 8192
                           + l0 + hh * 4] = v;
        }
    }
}

// host-side PDL launch helper
template <typename K, typename... Args>
static void launch_pdl(K kernel, dim3 grid, dim3 block, Args... args) {
    cudaLaunchAttribute at[1];
    at[0].id = cudaLaunchAttributeProgrammaticStreamSerialization;
    at[0].val.programmaticStreamSerializationAllowed = 1;
    cudaLaunchConfig_t cfg = {};
    cfg.gridDim = grid;
    cfg.blockDim = block;
    cfg.dynamicSmemBytes = 0;
    cfg.stream = 0;
    cfg.attrs = at;
    cfg.numAttrs = 1;
    cudaLaunchKernelEx(&cfg, kernel, args...);
}

extern "C" void kernel_launch(void* const* d_in, const int* in_sizes, int n_in,
                              void* d_out, int out_size) {
    const float* x           = (const float*)d_in[0];
    const float* start_w     = (const float*)d_in[1];
    const float* start_b     = (const float*)d_in[2];
    const float* gate_w      = (const float*)d_in[3];
    const float* gate_b      = (const float*)d_in[4];
    const float* res_w       = (const float*)d_in[5];
    const float* res_b       = (const float*)d_in[6];
    const float* bn_g        = (const float*)d_in[7];
    const float* bn_b        = (const float*)d_in[8];
    const float* end_bn1_g   = (const float*)d_in[9];
    const float* end_bn1_b   = (const float*)d_in[10];
    const float* end_conv1_w = (const float*)d_in[11];
    const float* end_conv1_b = (const float*)d_in[12];
    const float* end_bn2_g   = (const float*)d_in[13];
    const float* end_bn2_b   = (const float*)d_in[14];
    const float* end_conv2_w = (const float*)d_in[15];
    const float* end_conv2_b = (const float*)d_in[16];
    float* out = (float*)d_out;

    k_prep<<<336, 512>>>();
    launch_pdl(k_start, dim3(256), dim3(256),
               x, start_w, start_b, gate_w, gate_b, res_w, res_b);
    for (int i = 1; i < 40; i++)
        launch_pdl(k_layer, dim3(1024), dim3(64),
                   gate_w, gate_b, res_w, res_b, bn_g, bn_b, i);
    launch_pdl(k_endA, dim3(1024), dim3(64), bn_g, bn_b);
    launch_pdl(k_endB, dim3(1024), dim3(256),
               end_bn1_g, end_bn1_b, end_conv1_w, end_conv1_b);
    launch_pdl(k_endC, dim3(1024), dim3(256),
               end_bn2_g, end_bn2_b, end_conv2_w, end_conv2_b, out);
}

// round 16
// speedup vs baseline: 1.2450x; 1.0829x over previous
#include <cuda_runtime.h>

typedef unsigned long long u64;
#define NPOS 65536
#define NPOSf 65536.0f
#define NPART 16
#define SBST 36

// persistent scratch (device globals)
__device__ float2 g_x2[16 * NPOS];              // residual stream x, ch-paired
__device__ float  g_rp[32 * NPOS];              // pre-BN layer output r, plain [ch][pos]
__device__ float4 g_xf[8 * NPOS];               // final x, channel quads
__device__ float  g_z[128 * NPOS];              // end_conv1 output
__device__ float  g_statp[NPART][42][2][128];   // partitioned stats

__device__ __forceinline__ float* stat_ptr(int part, int op, int kind) {
    return &g_statp[part][op][kind][0];
}

__device__ __forceinline__ void fma2(u64 &d, u64 a, u64 b, u64 c) {
    asm("fma.rn.f32x2 %0, %1, %2, %3;" : "=l"(d) : "l"(a), "l"(b), "l"(c));
}
__device__ __forceinline__ u64 pack2(float f) {
    u64 r; unsigned b = __float_as_uint(f);
    asm("mov.b64 %0, {%1, %1};" : "=l"(r) : "r"(b));
    return r;
}
__device__ __forceinline__ float lo2(u64 v) { return __uint_as_float((unsigned)v); }
__device__ __forceinline__ float hi2(u64 v) { return __uint_as_float((unsigned)(v >> 32)); }

__device__ __forceinline__ float mishf(float v) {
    float u = __expf(fminf(fmaxf(v, -20.0f), 20.0f));
    float w = fmaf(u, u, u + u);
    return v * __fdividef(w, w + 2.0f);
}

// mish(a) and mish(-a) sharing one exp
__device__ __forceinline__ void mish_pair(float a, float &mp, float &mn) {
    float ac = fminf(fmaxf(a, -20.0f), 20.0f);
    float u = __expf(ac);
    float A = fmaf(u, u, u + u);
    mp = a * __fdividef(A, A + 2.0f);
    float B = fmaf(2.0f, u, 1.0f);
    mn = -a * __fdividef(B, fmaf(u + u, u, B));
}

// ---- tf32 helpers ----
__device__ __forceinline__ unsigned cvt_tf32(float f) {
    unsigned r; asm("cvt.rna.tf32.f32 %0, %1;" : "=r"(r) : "f"(f)); return r;
}
__device__ __forceinline__ void split_tf32(float f, unsigned &hi, unsigned &lo) {
    hi = cvt_tf32(f);
    lo = cvt_tf32(f - __uint_as_float(hi));
}
__device__ __forceinline__ void mma_tf32(float* c, const unsigned* a,
                                         unsigned b0, unsigned b1) {
    asm("mma.sync.aligned.m16n8k8.row.col.f32.tf32.tf32.f32 "
        "{%0,%1,%2,%3}, {%4,%5,%6,%7}, {%8,%9}, {%0,%1,%2,%3};"
        : "+f"(c[0]), "+f"(c[1]), "+f"(c[2]), "+f"(c[3])
        : "r"(a[0]), "r"(a[1]), "r"(a[2]), "r"(a[3]), "r"(b0), "r"(b1));
}

// legacy reduction (k_start, 256 threads)
template<int BS>
__device__ __forceinline__ void reduce_stats(float* red, float* part1, float* part2,
                                             const float* vals, int tid,
                                             int prt, int op, int coff) {
    __syncthreads();
    #pragma unroll
    for (int c = 0; c < 32; c++) red[tid * 34 + c] = vals[c];
    __syncthreads();
    {
        int c = tid & 31, seg = tid >> 5;
        int base = seg * 32;
        float s = 0.f, q = 0.f;
        #pragma unroll
        for (int r = 0; r < 32; r++) {
            float v = red[(base + r) * 34 + c];
            s += v;
            q = fmaf(v, v, q);
        }
        part1[seg * 32 + c] = s;
        part2[seg * 32 + c] = q;
    }
    __syncthreads();
    if (tid < 64) {
        int c = tid & 31, kind = tid >> 5;
        const float* pp = kind ? part2 : part1;
        float t = 0.f;
        #pragma unroll
        for (int sg = 0; sg < BS / 32; sg++) t += pp[sg * 32 + c];
        atomicAdd(stat_ptr(prt, op, kind) + coff + c, t);
    }
}

// float4-vectorized reduction for 64-thread blocks; vals[32] per thread.
__device__ __forceinline__ void reduce64(float4* red4, float4* ps, float4* pq,
                                         const float* vals, int tid,
                                         int prt, int op) {
    __syncthreads();
    #pragma unroll
    for (int q = 0; q < 8; q++)
        red4[q * 65 + tid] = make_float4(vals[4 * q], vals[4 * q + 1],
                                         vals[4 * q + 2], vals[4 * q + 3]);
    __syncthreads();
    {
        int q = tid & 7, seg = tid >> 3;
        float4 s = make_float4(0.f, 0.f, 0.f, 0.f);
        float4 sq = make_float4(0.f, 0.f, 0.f, 0.f);
        #pragma unroll
        for (int r = 0; r < 8; r++) {
            float4 v = red4[q * 65 + seg * 8 + r];
            s.x += v.x; s.y += v.y; s.z += v.z; s.w += v.w;
            sq.x = fmaf(v.x, v.x, sq.x);
            sq.y = fmaf(v.y, v.y, sq.y);
            sq.z = fmaf(v.z, v.z, sq.z);
            sq.w = fmaf(v.w, v.w, sq.w);
        }
        ps[seg * 8 + q] = s;
        pq[seg * 8 + q] = sq;
    }
    __syncthreads();
    {
        int c = tid & 31, kind = tid >> 5;
        int quad = c >> 2, comp = c & 3;
        const float* base = (const float*)(kind ? pq : ps);
        float t = 0.f;
        #pragma unroll
        for (int seg = 0; seg < 8; seg++)
            t += base[(seg * 8 + quad) * 4 + comp];
        atomicAdd(stat_ptr(prt, op, kind) + c, t);
    }
}

// combine partitioned stats -> BN scale/shift (threads 0..31)
__device__ __forceinline__ void bn_combine32(const float* g, const float* b, int op,
                                             float* s_scale, float* s_shift, int tid) {
    if (tid < 32) {
        float s = 0.f, q = 0.f;
        #pragma unroll
        for (int pp = 0; pp < NPART; pp++) {
            s += g_statp[pp][op][0][tid];
            q += g_statp[pp][op][1][tid];
        }
        float m = s * (1.0f / NPOSf);
        float var = q * (1.0f / NPOSf) - m * m;
        float inv = rsqrtf(var + 1e-5f);
        float sc = g[tid] * inv;
        s_scale[tid] = sc;
        s_shift[tid] = b[tid] - m * sc;
    }
}

// full-width paired gate(16x32)->concat-mish->res(32x32) (k_start only)
__device__ __forceinline__ void gate_res_p(const float* xn, float* rn,
                                           const float* s_gw, const float* s_gb,
                                           const float* s_rw, const float* s_rb) {
    u64 accg[8];
    #pragma unroll
    for (int jp = 0; jp < 8; jp++) accg[jp] = *(const u64*)&s_gb[2 * jp];
    const ulonglong2* gw2 = (const ulonglong2*)s_gw;
    #pragma unroll
    for (int k = 0; k < 32; k++) {
        u64 xk = pack2(xn[k]);
        #pragma unroll
        for (int m = 0; m < 4; m++) {
            ulonglong2 w = gw2[k * 4 + m];
            fma2(accg[2 * m],     w.x, xk, accg[2 * m]);
            fma2(accg[2 * m + 1], w.y, xk, accg[2 * m + 1]);
        }
    }
    float cm[32];
    #pragma unroll
    for (int jp = 0; jp < 8; jp++) {
        float a0 = lo2(accg[jp]), a1 = hi2(accg[jp]);
        mish_pair(a0, cm[2 * jp],     cm[2 * jp + 16]);
        mish_pair(a1, cm[2 * jp + 1], cm[2 * jp + 17]);
    }
    u64 accr[16];
    #pragma unroll
    for (int cp = 0; cp < 16; cp++) accr[cp] = *(const u64*)&s_rb[2 * cp];
    const ulonglong2* rw2 = (const ulonglong2*)s_rw;
    #pragma unroll
    for (int k = 0; k < 32; k++) {
        u64 ck = pack2(cm[k]);
        #pragma unroll
        for (int m = 0; m < 8; m++) {
            ulonglong2 w = rw2[k * 8 + m];
            fma2(accr[2 * m],     w.x, ck, accr[2 * m]);
            fma2(accr[2 * m + 1], w.y, ck, accr[2 * m + 1]);
        }
    }
    #pragma unroll
    for (int cp = 0; cp < 16; cp++) {
        rn[2 * cp]     = lo2(accr[cp]);
        rn[2 * cp + 1] = hi2(accr[cp]);
    }
}

__global__ void k_prep() {
    int idx = blockIdx.x * 512 + threadIdx.x;
    float* st = &g_statp[0][0][0][0];
    if (idx < NPART * 42 * 2 * 128) st[idx] = 0.f;
}

// start conv (32x256) + layer-0 gate/res + stats[0]
__global__ __launch_bounds__(256, 2) void k_start(
    const float* __restrict__ xin,
    const float* __restrict__ start_w, const float* __restrict__ start_b,
    const float* __restrict__ gate_w, const float* __restrict__ gate_b,
    const float* __restrict__ res_w, const float* __restrict__ res_b)
{
    __shared__ __align__(16) float s_red[256 * 34];
    __shared__ float s_p1[256], s_p2[256];
    __shared__ __align__(16) float s_gw[512];
    __shared__ __align__(16) float s_rw[1024];
    __shared__ __align__(8) float s_gb[16];
    __shared__ __align__(8) float s_rb[32];
    __shared__ __align__(8) float s_sb[32];

    int tid = threadIdx.x;
    int p = blockIdx.x * 256 + tid;
    int prt = blockIdx.x & (NPART - 1);

    for (int idx = tid; idx < 8192; idx += 256) {
        int k = idx >> 5, c = idx & 31;
        s_red[k * 32 + c] = start_w[c * 256 + k];
    }
    for (int i = tid; i < 512; i += 256)  { int j = i & 15, k = i >> 4; s_gw[i] = gate_w[j * 32 + k]; }
    for (int i = tid; i < 1024; i += 256) { int c = i & 31, k = i >> 5; s_rw[i] = res_w[c * 32 + k]; }
    if (tid < 16) s_gb[tid] = gate_b[tid];
    if (tid >= 32 && tid < 64) s_rb[tid - 32] = res_b[tid - 32];
    if (tid >= 64 && tid < 96) s_sb[tid - 64] = start_b[tid - 64];
    __syncthreads();

    u64 acc[16];
    #pragma unroll
    for (int cp = 0; cp < 16; cp++) acc[cp] = *(const u64*)&s_sb[2 * cp];
    const float* xp = xin + (size_t)(p & 7) * (256 * 8192) + (p >> 3);
    const ulonglong2* swT2 = (const ulonglong2*)s_red;
    #pragma unroll 4
    for (int k = 0; k < 256; k++) {
        u64 xk = pack2(xp[k * 8192]);
        #pragma unroll
        for (int m = 0; m < 8; m++) {
            ulonglong2 w = swT2[k * 8 + m];
            fma2(acc[2 * m],     w.x, xk, acc[2 * m]);
            fma2(acc[2 * m + 1], w.y, xk, acc[2 * m + 1]);
        }
    }
    float xn[32];
    #pragma unroll
    for (int cp = 0; cp < 16; cp++) {
        xn[2 * cp] = lo2(acc[cp]);
        xn[2 * cp + 1] = hi2(acc[cp]);
        g_x2[cp * NPOS + p] = make_float2(xn[2 * cp], xn[2 * cp + 1]);
    }
    float rn[32];
    gate_res_p(xn, rn, s_gw, s_gb, s_rw, s_rb);
    #pragma unroll
    for (int c = 0; c < 32; c++) g_rp[c * NPOS + p] = rn[c];

    reduce_stats<256>(s_red, s_p1, s_p2, rn, tid, prt, 0, 0);
}

// ============ tf32 MMA layer kernel (kt-outer interleaved MMA chains) ============
// block = 64 threads = 2 warps; warp handles 32 positions.
__global__ __launch_bounds__(64, 7) void k_layer(
    const float* __restrict__ gate_w, const float* __restrict__ gate_b,
    const float* __restrict__ res_w, const float* __restrict__ res_b,
    const float* __restrict__ bn_g, const float* __restrict__ bn_b,
    int layer)
{
    __shared__ __align__(16) float sbuf[64 * SBST];   // [pos][ch] then [pos][cm]
    __shared__ __align__(16) float s_gw[512];         // [j][k]
    __shared__ __align__(16) float s_rw[1024];        // [c][k]
    __shared__ float s_gb[16], s_rb[32];
    __shared__ float s_scale[32], s_shift[32];
    __shared__ float s_st[2][32];

    int tid = threadIdx.x;
    int w = tid >> 5, l = tid & 31;
    int gr = l >> 2, gc = l & 3;
    int prt = blockIdx.x & (NPART - 1);
    int lp = 32 * w + l;
    int p = blockIdx.x * 64 + lp;
    int pb = blockIdx.x * 64 + 32 * w;   // warp position base

    // stage weights (straight copy)
    #pragma unroll
    for (int i = tid; i < 128; i += 64)
        *(float4*)&s_gw[4 * i] = *(const float4*)&gate_w[layer * 512 + 4 * i];
    #pragma unroll
    for (int i = tid; i < 256; i += 64)
        *(float4*)&s_rw[4 * i] = *(const float4*)&res_w[layer * 1024 + 4 * i];
    if (tid < 16) s_gb[tid] = gate_b[layer * 16 + tid];
    if (tid >= 32) s_rb[tid - 32] = res_b[layer * 32 + tid - 32];
    bn_combine32(bn_g + (layer - 1) * 32, bn_b + (layer - 1) * 32, layer - 1,
                 s_scale, s_shift, tid);
    if (tid < 32) { s_st[0][tid] = 0.f; s_st[1][tid] = 0.f; }
    __syncthreads();

    // ---- phase A: BN + residual; x' -> gmem and sbuf[pos][ch] ----
    float xn[32];
    #pragma unroll
    for (int m = 0; m < 16; m++) {
        float2 xv = g_x2[m * NPOS + p];
        float r0 = g_rp[(2 * m) * NPOS + p];
        float r1 = g_rp[(2 * m + 1) * NPOS + p];
        float v0 = fmaf(s_scale[2 * m],     r0, xv.x + s_shift[2 * m]);
        float v1 = fmaf(s_scale[2 * m + 1], r1, xv.y + s_shift[2 * m + 1]);
        xn[2 * m] = v0; xn[2 * m + 1] = v1;
        g_x2[m * NPOS + p] = make_float2(v0, v1);
    }
    #pragma unroll
    for (int qd = 0; qd < 8; qd++)
        *(float4*)&sbuf[lp * SBST + 4 * qd] =
            make_float4(xn[4 * qd], xn[4 * qd + 1], xn[4 * qd + 2], xn[4 * qd + 3]);
    __syncwarp();

    // ---- gate A fragments (tf32 split) ----
    unsigned gah[4][4], gal[4][4];
    #pragma unroll
    for (int kt = 0; kt < 4; kt++) {
        split_tf32(s_gw[gr * 32 + kt * 8 + gc],           gah[kt][0], gal[kt][0]);
        split_tf32(s_gw[(gr + 8) * 32 + kt * 8 + gc],     gah[kt][1], gal[kt][1]);
        split_tf32(s_gw[gr * 32 + kt * 8 + gc + 4],       gah[kt][2], gal[kt][2]);
        split_tf32(s_gw[(gr + 8) * 32 + kt * 8 + gc + 4], gah[kt][3], gal[kt][3]);
    }

    // ---- gate GEMM m16 n32 k32, kt outer: 4 independent accumulator chains ----
    float gC[4][4];
    #pragma unroll
    for (int nt = 0; nt < 4; nt++) {
        gC[nt][0] = gC[nt][1] = s_gb[gr];
        gC[nt][2] = gC[nt][3] = s_gb[gr + 8];
    }
    #pragma unroll
    for (int kt = 0; kt < 4; kt++) {
        unsigned b0h[4], b0l[4], b1h[4], b1l[4];
        #pragma unroll
        for (int nt = 0; nt < 4; nt++) {
            int row = (32 * w + nt * 8 + gr) * SBST + kt * 8 + gc;
            split_tf32(sbuf[row],     b0h[nt], b0l[nt]);
            split_tf32(sbuf[row + 4], b1h[nt], b1l[nt]);
        }
        #pragma unroll
        for (int nt = 0; nt < 4; nt++) mma_tf32(gC[nt], gah[kt], b0h[nt], b1h[nt]);
        #pragma unroll
        for (int nt = 0; nt < 4; nt++) mma_tf32(gC[nt], gah[kt], b0l[nt], b1l[nt]);
        #pragma unroll
        for (int nt = 0; nt < 4; nt++) mma_tf32(gC[nt], gal[kt], b0h[nt], b1h[nt]);
    }
    __syncwarp();   // all gate B reads done before cm overwrites sbuf

    // ---- concat-mish -> sbuf[pos][cm] ----
    #pragma unroll
    for (int nt = 0; nt < 4; nt++) {
        int r0 = (32 * w + nt * 8 + 2 * gc) * SBST;
        int r1 = r0 + SBST;
        float mp, mn;
        mish_pair(gC[nt][0], mp, mn);
        sbuf[r0 + gr] = mp;      sbuf[r0 + gr + 16] = mn;
        mish_pair(gC[nt][1], mp, mn);
        sbuf[r1 + gr] = mp;      sbuf[r1 + gr + 16] = mn;
        mish_pair(gC[nt][2], mp, mn);
        sbuf[r0 + gr + 8] = mp;  sbuf[r0 + gr + 24] = mn;
        mish_pair(gC[nt][3], mp, mn);
        sbuf[r1 + gr + 8] = mp;  sbuf[r1 + gr + 24] = mn;
    }
    __syncwarp();

    // ---- res A fragments ----
    unsigned rah[2][4][4], ral[2][4][4];
    #pragma unroll
    for (int mt = 0; mt < 2; mt++)
        #pragma unroll
        for (int kt = 0; kt < 4; kt++) {
            int rbase = (16 * mt + gr) * 32 + kt * 8 + gc;
            split_tf32(s_rw[rbase],           rah[mt][kt][0], ral[mt][kt][0]);
            split_tf32(s_rw[rbase + 256],     rah[mt][kt][1], ral[mt][kt][1]);
            split_tf32(s_rw[rbase + 4],       rah[mt][kt][2], ral[mt][kt][2]);
            split_tf32(s_rw[rbase + 260],     rah[mt][kt][3], ral[mt][kt][3]);
        }

    // ---- res GEMM m32 n32 k32, kt outer: 8 independent accumulator chains ----
    float rC[2][4][4];
    #pragma unroll
    for (int mt = 0; mt < 2; mt++)
        #pragma unroll
        for (int nt = 0; nt < 4; nt++) {
            rC[mt][nt][0] = rC[mt][nt][1] = s_rb[16 * mt + gr];
            rC[mt][nt][2] = rC[mt][nt][3] = s_rb[16 * mt + gr + 8];
        }
    #pragma unroll
    for (int kt = 0; kt < 4; kt++) {
        unsigned b0h[4], b0l[4], b1h[4], b1l[4];
        #pragma unroll
        for (int nt = 0; nt < 4; nt++) {
            int row = (32 * w + nt * 8 + gr) * SBST + kt * 8 + gc;
            split_tf32(sbuf[row],     b0h[nt], b0l[nt]);
            split_tf32(sbuf[row + 4], b1h[nt], b1l[nt]);
        }
        #pragma unroll
        for (int nt = 0; nt < 4; nt++) mma_tf32(rC[0][nt], rah[0][kt], b0h[nt], b1h[nt]);
        #pragma unroll
        for (int nt = 0; nt < 4; nt++) mma_tf32(rC[1][nt], rah[1][kt], b0h[nt], b1h[nt]);
        #pragma unroll
        for (int nt = 0; nt < 4; nt++) mma_tf32(rC[0][nt], rah[0][kt], b0l[nt], b1l[nt]);
        #pragma unroll
        for (int nt = 0; nt < 4; nt++) mma_tf32(rC[1][nt], rah[1][kt], b0l[nt], b1l[nt]);
        #pragma unroll
        for (int nt = 0; nt < 4; nt++) mma_tf32(rC[0][nt], ral[0][kt], b0h[nt], b1h[nt]);
        #pragma unroll
        for (int nt = 0; nt < 4; nt++) mma_tf32(rC[1][nt], ral[1][kt], b0h[nt], b1h[nt]);
    }

    // ---- store r + per-lane stat partials ----
    float s4[4] = {0.f, 0.f, 0.f, 0.f}, q4[4] = {0.f, 0.f, 0.f, 0.f};
    #pragma unroll
    for (int mt = 0; mt < 2; mt++)
        #pragma unroll
        for (int nt = 0; nt < 4; nt++) {
            int c0r = 16 * mt + gr, c1r = c0r + 8;
            int pcol = nt * 8 + 2 * gc;
            float a0 = rC[mt][nt][0], a1 = rC[mt][nt][1];
            float a2 = rC[mt][nt][2], a3 = rC[mt][nt][3];
            *(float2*)&g_rp[(size_t)c0r * NPOS + pb + pcol] = make_float2(a0, a1);
            *(float2*)&g_rp[(size_t)c1r * NPOS + pb + pcol] = make_float2(a2, a3);
            s4[2 * mt]     += a0 + a1;
            q4[2 * mt]      = fmaf(a0, a0, fmaf(a1, a1, q4[2 * mt]));
            s4[2 * mt + 1] += a2 + a3;
            q4[2 * mt + 1]  = fmaf(a2, a2, fmaf(a3, a3, q4[2 * mt + 1]));
        }
    // quad reduce over gc; lane gc==0 owns channels gr + 8*i
    #pragma unroll
    for (int d = 1; d < 4; d <<= 1) {
        #pragma unroll
        for (int i = 0; i < 4; i++) {
            s4[i] += __shfl_xor_sync(0xffffffffu, s4[i], d);
            q4[i] += __shfl_xor_sync(0xffffffffu, q4[i], d);
        }
    }
    if (gc == 0) {
        #pragma unroll
        for (int i = 0; i < 4; i++) {
            atomicAdd(&s_st[0][gr + 8 * i], s4[i]);
            atomicAdd(&s_st[1][gr + 8 * i], q4[i]);
        }
    }
    __syncthreads();
    if (tid < 64) {
        int c = tid & 31, kind = tid >> 5;
        atomicAdd(stat_ptr(prt, layer, kind) + c, s_st[kind][c]);
    }
}

// apply BN(39) + residual -> final x into g_xf; stats[40]
__global__ __launch_bounds__(64, 7) void k_endA(
    const float* __restrict__ bn_g, const float* __restrict__ bn_b)
{
    __shared__ __align__(16) float4 s_red4[8 * 65];
    __shared__ __align__(16) float4 s_ps[64], s_pq[64];
    __shared__ float s_scale[32], s_shift[32];
    int tid = threadIdx.x;
    int p = blockIdx.x * 64 + tid;
    int prt = blockIdx.x & (NPART - 1);
    bn_combine32(bn_g + 39 * 32, bn_b + 39 * 32, 39, s_scale, s_shift, tid);
    __syncthreads();
    float xn[32];
    #pragma unroll
    for (int m = 0; m < 16; m++) {
        float2 xv = g_x2[m * NPOS + p];
        float r0 = g_rp[(2 * m) * NPOS + p];
        float r1 = g_rp[(2 * m + 1) * NPOS + p];
        xn[2 * m]     = fmaf(s_scale[2 * m],     r0, xv.x + s_shift[2 * m]);
        xn[2 * m + 1] = fmaf(s_scale[2 * m + 1], r1, xv.y + s_shift[2 * m + 1]);
    }
    #pragma unroll
    for (int cq = 0; cq < 8; cq++)
        g_xf[cq * NPOS + p] = make_float4(xn[4 * cq], xn[4 * cq + 1],
                                          xn[4 * cq + 2], xn[4 * cq + 3]);
    reduce64(s_red4, s_ps, s_pq, xn, tid, prt, 40);
}

// tiled end_conv1: z[128] = W1 @ concat_mish(bn1(x)); stats[41]
__global__ __launch_bounds__(256, 3) void k_endB(
    const float* __restrict__ bn1_g, const float* __restrict__ bn1_b,
    const float* __restrict__ w1, const float* __restrict__ b1)
{
    __shared__ __align__(16) float s_w[128 * 68];
    __shared__ __align__(16) float s_y[64 * 68];
    __shared__ float s_ps[128 * 17], s_pq[128 * 17];
    __shared__ float s_scale[32], s_shift[32];

    int tid = threadIdx.x;
    int p0 = blockIdx.x * 64;
    int prt = blockIdx.x & (NPART - 1);

    bn_combine32(bn1_g, bn1_b, 40, s_scale, s_shift, tid);

    #pragma unroll
    for (int i = tid * 4; i < 8192; i += 1024) {
        float4 v = *(const float4*)(w1 + i);
        int o = i >> 6, k = i & 63;
        *(float4*)&s_w[o * 68 + k] = v;
    }
    __syncthreads();

    #pragma unroll
    for (int it = 0; it < 2; it++) {
        int cq = (tid >> 6) + it * 4;
        int pos = tid & 63;
        float4 xq = g_xf[cq * NPOS + p0 + pos];
        float xv[4] = {xq.x, xq.y, xq.z, xq.w};
        #pragma unroll
        for (int u = 0; u < 4; u++) {
            int c = cq * 4 + u;
            float t = fmaf(s_scale[c], xv[u], s_shift[c]);
            float yp, yn;
            mish_pair(t, yp, yn);
            s_y[c * 68 + pos]        = yp;
            s_y[(c + 32) * 68 + pos] = yn;
        }
    }
    __syncthreads();

    int ty = tid >> 4;
    int tx = tid & 15;
    int o0 = ty * 8;
    u64 acc[8][2];
    #pragma unroll
    for (int i = 0; i < 8; i++) {
        u64 b = pack2(__ldg(b1 + o0 + i));
        acc[i][0] = b; acc[i][1] = b;
    }
    #pragma unroll 8
    for (int k = 0; k < 64; k++) {
        ulonglong2 yv = *(const ulonglong2*)&s_y[k * 68 + tx * 4];
        #pragma unroll
        for (int i = 0; i < 8; i++) {
            u64 w = pack2(s_w[(o0 + i) * 68 + k]);
            fma2(acc[i][0], w, yv.x, acc[i][0]);
            fma2(acc[i][1], w, yv.y, acc[i][1]);
        }
    }
    #pragma unroll
    for (int i = 0; i < 8; i++) {
        float a0 = lo2(acc[i][0]), a1 = hi2(acc[i][0]);
        float a2 = lo2(acc[i][1]), a3 = hi2(acc[i][1]);
        *(float4*)&g_z[(size_t)(o0 + i) * NPOS + p0 + tx * 4] =
            make_float4(a0, a1, a2, a3);
        s_ps[(o0 + i) * 17 + tx] = a0 + a1 + a2 + a3;
        s_pq[(o0 + i) * 17 + tx] =
            fmaf(a0, a0, fmaf(a1, a1, fmaf(a2, a2, a3 * a3)));
    }
    __syncthreads();
    {
        int o = tid & 127, kind = tid >> 7;
        const float* src = kind ? s_pq : s_ps;
        float t = 0.f;
        #pragma unroll
        for (int j = 0; j < 16; j++) t += src[o * 17 + j];
        atomicAdd(stat_ptr(prt, 41, kind) + o, t);
    }
}

// out = end_conv2 (256x256) @ concat_mish(bn2(z)); f32x2 packed FMA.
__global__ __launch_bounds__(256) void k_endC(
    const float* __restrict__ bn2_g, const float* __restrict__ bn2_b,
    const float* __restrict__ w2, const float* __restrict__ b2,
    float* __restrict__ out)
{
    __shared__ __align__(16) float sBuf[256 * 33 + 32 * 64];
    __shared__ float sSc[128], sSh[128], sB2[256];
    float* sW = sBuf;
    float* sV = sBuf + 256 * 33;

    int tid = threadIdx.x;
    int ty = tid >> 3;
    int tx = tid & 7;
    int p0 = blockIdx.x * 64;
    int l0 = p0 >> 3;

    if (tid < 128) {
        float s = 0.f, q = 0.f;
        #pragma unroll
        for (int pp = 0; pp < NPART; pp++) {
            s += g_statp[pp][41][0][tid];
            q += g_statp[pp][41][1][tid];
        }
        float m = s * (1.0f / NPOSf);
        float var = q * (1.0f / NPOSf) - m * m;
        float inv = rsqrtf(var + 1e-5f);
        float sc = bn2_g[tid] * inv;
        sSc[tid] = sc;
        sSh[tid] = bn2_b[tid] - m * sc;
    }
    sB2[tid] = b2[tid];

    u64 acc[8][4];
    #pragma unroll
    for (int i = 0; i < 8; i++)
        #pragma unroll
        for (int jp = 0; jp < 4; jp++) acc[i][jp] = 0ULL;

    for (int kc = 0; kc < 8; kc++) {
        __syncthreads();
        for (int idx = tid; idx < 8192; idx += 256) {
            int o = idx >> 5, k = idx & 31;
            sW[o * 33 + k] = w2[o * 256 + kc * 32 + k];
        }
        for (int idx = tid; idx < 2048; idx += 256) {
            int kk = idx >> 6, qq = idx & 63;
            int c = kc * 32 + kk;
            int zc = (c < 128) ? c : c - 128;
            float t = fmaf(sSc[zc], g_z[zc * NPOS + p0 + qq], sSh[zc]);
            sV[kk * 64 + qq] = mishf((c < 128) ? t : -t);
        }
        __syncthreads();
        int woff = ty * 8 * 33;
        int voff = tx * 8;
        #pragma unroll
        for (int k = 0; k < 32; k++) {
            u64 vv[4];
            #pragma unroll
            for (int jp = 0; jp < 4; jp++)
                vv[jp] = *(const u64*)&sV[k * 64 + voff + jp * 2];
            #pragma unroll
            for (int i = 0; i < 8; i++) {
                u64 wd = pack2(sW[woff + i * 33 + k]);
                #pragma unroll
                for (int jp = 0; jp < 4; jp++)
                    fma2(acc[i][jp], wd, vv[jp], acc[i][jp]);
            }
        }
    }

    for (int oh = 0; oh < 2; oh++) {
        __syncthreads();
        if ((ty >> 4) == oh) {
            int orow = (ty & 15) * 8;
            #pragma unroll
            for (int i = 0; i < 8; i++) {
                float bias = sB2[oh * 128 + orow + i];
                #pragma unroll
                for (int j = 0; j < 8; j++) {
                    int jp = j >> 1;
                    float f = (j & 1) ? hi2(acc[i][jp]) : lo2(acc[i][jp]);
                    sBuf[(orow + i) * 64 + j * 8 + tx] = f + bias;
                }
            }
        }
        __syncthreads();
        for (int idx = tid; idx < 2048; idx += 256) {
            int oloc = idx >> 4;
            int b = (idx >> 1) & 7;
            int hh = idx & 1;
            float4 v = *(float4*)&sBuf[oloc * 64 + b * 8 + hh * 4];
            *(float4*)&out[(size_t)b * 2097152 + (size_t)(oh * 128 + oloc) * 8192
                           + l0 + hh * 4] = v;
        }
    }
}

extern "C" void kernel_launch(void* const* d_in, const int* in_sizes, int n_in,
                              void* d_out, int out_size) {
    const float* x           = (const float*)d_in[0];
    const float* start_w     = (const float*)d_in[1];
    const float* start_b     = (const float*)d_in[2];
    const float* gate_w      = (const float*)d_in[3];
    const float* gate_b      = (const float*)d_in[4];
    const float* res_w       = (const float*)d_in[5];
    const float* res_b       = (const float*)d_in[6];
    const float* bn_g        = (const float*)d_in[7];
    const float* bn_b        = (const float*)d_in[8];
    const float* end_bn1_g   = (const float*)d_in[9];
    const float* end_bn1_b   = (const float*)d_in[10];
    const float* end_conv1_w = (const float*)d_in[11];
    const float* end_conv1_b = (const float*)d_in[12];
    const float* end_bn2_g   = (const float*)d_in[13];
    const float* end_bn2_b   = (const float*)d_in[14];
    const float* end_conv2_w = (const float*)d_in[15];
    const float* end_conv2_b = (const float*)d_in[16];
    float* out = (float*)d_out;

    k_prep<<<336, 512>>>();
    k_start<<<256, 256>>>(x, start_w, start_b, gate_w, gate_b, res_w, res_b);
    for (int i = 1; i < 40; i++)
        k_layer<<<1024, 64>>>(gate_w, gate_b, res_w, res_b, bn_g, bn_b, i);
    k_endA<<<1024, 64>>>(bn_g, bn_b);
    k_endB<<<1024, 256>>>(end_bn1_g, end_bn1_b, end_conv1_w, end_conv1_b);
    k_endC<<<1024, 256>>>(end_bn2_g, end_bn2_b, end_conv2_w, end_conv2_b, out);
}

// round 17
// speedup vs baseline: 1.2922x; 1.0379x over previous
#include <cuda_runtime.h>

typedef unsigned long long u64;
#define NPOS 65536
#define NPOSf 65536.0f
#define NPART 16
#define SBST 36

// persistent scratch (device globals)
__device__ float4 g_xr[16 * NPOS];              // (x0,x1,r0,r1) per channel-pair
__device__ float4 g_xf[8 * NPOS];               // final x, channel quads
__device__ float  g_z[128 * NPOS];              // end_conv1 output
__device__ float  g_statp[NPART][42][2][128];   // partitioned stats

__device__ __forceinline__ float* stat_ptr(int part, int op, int kind) {
    return &g_statp[part][op][kind][0];
}

__device__ __forceinline__ void fma2(u64 &d, u64 a, u64 b, u64 c) {
    asm("fma.rn.f32x2 %0, %1, %2, %3;" : "=l"(d) : "l"(a), "l"(b), "l"(c));
}
__device__ __forceinline__ u64 pack2(float f) {
    u64 r; unsigned b = __float_as_uint(f);
    asm("mov.b64 %0, {%1, %1};" : "=l"(r) : "r"(b));
    return r;
}
__device__ __forceinline__ float lo2(u64 v) { return __uint_as_float((unsigned)v); }
__device__ __forceinline__ float hi2(u64 v) { return __uint_as_float((unsigned)(v >> 32)); }

__device__ __forceinline__ float mishf(float v) {
    float u = __expf(fminf(fmaxf(v, -20.0f), 20.0f));
    float w = fmaf(u, u, u + u);
    return v * __fdividef(w, w + 2.0f);
}

// mish(a) and mish(-a) sharing one exp
__device__ __forceinline__ void mish_pair(float a, float &mp, float &mn) {
    float ac = fminf(fmaxf(a, -20.0f), 20.0f);
    float u = __expf(ac);
    float A = fmaf(u, u, u + u);
    mp = a * __fdividef(A, A + 2.0f);
    float B = fmaf(2.0f, u, 1.0f);
    mn = -a * __fdividef(B, fmaf(u + u, u, B));
}

// ---- tf32 helpers ----
__device__ __forceinline__ unsigned cvt_tf32(float f) {
    unsigned r; asm("cvt.rna.tf32.f32 %0, %1;" : "=r"(r) : "f"(f)); return r;
}
__device__ __forceinline__ void split_tf32(float f, unsigned &hi, unsigned &lo) {
    hi = cvt_tf32(f);
    lo = cvt_tf32(f - __uint_as_float(hi));
}
__device__ __forceinline__ void mma_tf32(float* c, const unsigned* a,
                                         unsigned b0, unsigned b1) {
    asm("mma.sync.aligned.m16n8k8.row.col.f32.tf32.tf32.f32 "
        "{%0,%1,%2,%3}, {%4,%5,%6,%7}, {%8,%9}, {%0,%1,%2,%3};"
        : "+f"(c[0]), "+f"(c[1]), "+f"(c[2]), "+f"(c[3])
        : "r"(a[0]), "r"(a[1]), "r"(a[2]), "r"(a[3]), "r"(b0), "r"(b1));
}

// legacy reduction (k_start, 256 threads)
template<int BS>
__device__ __forceinline__ void reduce_stats(float* red, float* part1, float* part2,
                                             const float* vals, int tid,
                                             int prt, int op, int coff) {
    __syncthreads();
    #pragma unroll
    for (int c = 0; c < 32; c++) red[tid * 34 + c] = vals[c];
    __syncthreads();
    {
        int c = tid & 31, seg = tid >> 5;
        int base = seg * 32;
        float s = 0.f, q = 0.f;
        #pragma unroll
        for (int r = 0; r < 32; r++) {
            float v = red[(base + r) * 34 + c];
            s += v;
            q = fmaf(v, v, q);
        }
        part1[seg * 32 + c] = s;
        part2[seg * 32 + c] = q;
    }
    __syncthreads();
    if (tid < 64) {
        int c = tid & 31, kind = tid >> 5;
        const float* pp = kind ? part2 : part1;
        float t = 0.f;
        #pragma unroll
        for (int sg = 0; sg < BS / 32; sg++) t += pp[sg * 32 + c];
        atomicAdd(stat_ptr(prt, op, kind) + coff + c, t);
    }
}

// float4-vectorized reduction for 64-thread blocks; vals[32] per thread.
__device__ __forceinline__ void reduce64(float4* red4, float4* ps, float4* pq,
                                         const float* vals, int tid,
                                         int prt, int op) {
    __syncthreads();
    #pragma unroll
    for (int q = 0; q < 8; q++)
        red4[q * 65 + tid] = make_float4(vals[4 * q], vals[4 * q + 1],
                                         vals[4 * q + 2], vals[4 * q + 3]);
    __syncthreads();
    {
        int q = tid & 7, seg = tid >> 3;
        float4 s = make_float4(0.f, 0.f, 0.f, 0.f);
        float4 sq = make_float4(0.f, 0.f, 0.f, 0.f);
        #pragma unroll
        for (int r = 0; r < 8; r++) {
            float4 v = red4[q * 65 + seg * 8 + r];
            s.x += v.x; s.y += v.y; s.z += v.z; s.w += v.w;
            sq.x = fmaf(v.x, v.x, sq.x);
            sq.y = fmaf(v.y, v.y, sq.y);
            sq.z = fmaf(v.z, v.z, sq.z);
            sq.w = fmaf(v.w, v.w, sq.w);
        }
        ps[seg * 8 + q] = s;
        pq[seg * 8 + q] = sq;
    }
    __syncthreads();
    {
        int c = tid & 31, kind = tid >> 5;
        int quad = c >> 2, comp = c & 3;
        const float* base = (const float*)(kind ? pq : ps);
        float t = 0.f;
        #pragma unroll
        for (int seg = 0; seg < 8; seg++)
            t += base[(seg * 8 + quad) * 4 + comp];
        atomicAdd(stat_ptr(prt, op, kind) + c, t);
    }
}

// combine partitioned stats -> BN scale/shift (threads 0..31)
__device__ __forceinline__ void bn_combine32(const float* g, const float* b, int op,
                                             float* s_scale, float* s_shift, int tid) {
    if (tid < 32) {
        float s = 0.f, q = 0.f;
        #pragma unroll
        for (int pp = 0; pp < NPART; pp++) {
            s += g_statp[pp][op][0][tid];
            q += g_statp[pp][op][1][tid];
        }
        float m = s * (1.0f / NPOSf);
        float var = q * (1.0f / NPOSf) - m * m;
        float inv = rsqrtf(var + 1e-5f);
        float sc = g[tid] * inv;
        s_scale[tid] = sc;
        s_shift[tid] = b[tid] - m * sc;
    }
}

// full-width paired gate(16x32)->concat-mish->res(32x32) (k_start only)
__device__ __forceinline__ void gate_res_p(const float* xn, float* rn,
                                           const float* s_gw, const float* s_gb,
                                           const float* s_rw, const float* s_rb) {
    u64 accg[8];
    #pragma unroll
    for (int jp = 0; jp < 8; jp++) accg[jp] = *(const u64*)&s_gb[2 * jp];
    const ulonglong2* gw2 = (const ulonglong2*)s_gw;
    #pragma unroll
    for (int k = 0; k < 32; k++) {
        u64 xk = pack2(xn[k]);
        #pragma unroll
        for (int m = 0; m < 4; m++) {
            ulonglong2 w = gw2[k * 4 + m];
            fma2(accg[2 * m],     w.x, xk, accg[2 * m]);
            fma2(accg[2 * m + 1], w.y, xk, accg[2 * m + 1]);
        }
    }
    float cm[32];
    #pragma unroll
    for (int jp = 0; jp < 8; jp++) {
        float a0 = lo2(accg[jp]), a1 = hi2(accg[jp]);
        mish_pair(a0, cm[2 * jp],     cm[2 * jp + 16]);
        mish_pair(a1, cm[2 * jp + 1], cm[2 * jp + 17]);
    }
    u64 accr[16];
    #pragma unroll
    for (int cp = 0; cp < 16; cp++) accr[cp] = *(const u64*)&s_rb[2 * cp];
    const ulonglong2* rw2 = (const ulonglong2*)s_rw;
    #pragma unroll
    for (int k = 0; k < 32; k++) {
        u64 ck = pack2(cm[k]);
        #pragma unroll
        for (int m = 0; m < 8; m++) {
            ulonglong2 w = rw2[k * 8 + m];
            fma2(accr[2 * m],     w.x, ck, accr[2 * m]);
            fma2(accr[2 * m + 1], w.y, ck, accr[2 * m + 1]);
        }
    }
    #pragma unroll
    for (int cp = 0; cp < 16; cp++) {
        rn[2 * cp]     = lo2(accr[cp]);
        rn[2 * cp + 1] = hi2(accr[cp]);
    }
}

__global__ void k_prep() {
    int idx = blockIdx.x * 512 + threadIdx.x;
    float* st = &g_statp[0][0][0][0];
    if (idx < NPART * 42 * 2 * 128) st[idx] = 0.f;
}

// start conv (32x256) + layer-0 gate/res + stats[0]; writes g_xr float4
__global__ __launch_bounds__(256, 2) void k_start(
    const float* __restrict__ xin,
    const float* __restrict__ start_w, const float* __restrict__ start_b,
    const float* __restrict__ gate_w, const float* __restrict__ gate_b,
    const float* __restrict__ res_w, const float* __restrict__ res_b)
{
    __shared__ __align__(16) float s_red[256 * 34];
    __shared__ float s_p1[256], s_p2[256];
    __shared__ __align__(16) float s_gw[512];
    __shared__ __align__(16) float s_rw[1024];
    __shared__ __align__(8) float s_gb[16];
    __shared__ __align__(8) float s_rb[32];
    __shared__ __align__(8) float s_sb[32];

    int tid = threadIdx.x;
    int p = blockIdx.x * 256 + tid;
    int prt = blockIdx.x & (NPART - 1);

    for (int idx = tid; idx < 8192; idx += 256) {
        int k = idx >> 5, c = idx & 31;
        s_red[k * 32 + c] = start_w[c * 256 + k];
    }
    for (int i = tid; i < 512; i += 256)  { int j = i & 15, k = i >> 4; s_gw[i] = gate_w[j * 32 + k]; }
    for (int i = tid; i < 1024; i += 256) { int c = i & 31, k = i >> 5; s_rw[i] = res_w[c * 32 + k]; }
    if (tid < 16) s_gb[tid] = gate_b[tid];
    if (tid >= 32 && tid < 64) s_rb[tid - 32] = res_b[tid - 32];
    if (tid >= 64 && tid < 96) s_sb[tid - 64] = start_b[tid - 64];
    __syncthreads();

    u64 acc[16];
    #pragma unroll
    for (int cp = 0; cp < 16; cp++) acc[cp] = *(const u64*)&s_sb[2 * cp];
    const float* xp = xin + (size_t)(p & 7) * (256 * 8192) + (p >> 3);
    const ulonglong2* swT2 = (const ulonglong2*)s_red;
    #pragma unroll 4
    for (int k = 0; k < 256; k++) {
        u64 xk = pack2(xp[k * 8192]);
        #pragma unroll
        for (int m = 0; m < 8; m++) {
            ulonglong2 w = swT2[k * 8 + m];
            fma2(acc[2 * m],     w.x, xk, acc[2 * m]);
            fma2(acc[2 * m + 1], w.y, xk, acc[2 * m + 1]);
        }
    }
    float xn[32];
    #pragma unroll
    for (int cp = 0; cp < 16; cp++) {
        xn[2 * cp] = lo2(acc[cp]);
        xn[2 * cp + 1] = hi2(acc[cp]);
    }
    float rn[32];
    gate_res_p(xn, rn, s_gw, s_gb, s_rw, s_rb);
    #pragma unroll
    for (int cp = 0; cp < 16; cp++)
        g_xr[cp * NPOS + p] = make_float4(xn[2 * cp], xn[2 * cp + 1],
                                          rn[2 * cp], rn[2 * cp + 1]);

    reduce_stats<256>(s_red, s_p1, s_p2, rn, tid, prt, 0, 0);
}

// ============ pos-M tf32 MMA layer kernel ============
// block = 64 threads = 2 warps; warp handles 32 positions (M dim).
// Channels are the N dim -> C-fragment cols are ADJACENT channels.
// Weights presplit hi/lo into smem at staging (stride 36: conflict-free).
__global__ __launch_bounds__(64, 7) void k_layer(
    const float* __restrict__ gate_w, const float* __restrict__ gate_b,
    const float* __restrict__ res_w, const float* __restrict__ res_b,
    const float* __restrict__ bn_g, const float* __restrict__ bn_b,
    int layer)
{
    __shared__ __align__(16) float sbuf[64 * SBST];   // [pos][ch] then [pos][cm]
    __shared__ unsigned s_gwh[16 * 36], s_gwl[16 * 36];   // [j][k] presplit
    __shared__ unsigned s_rwh[32 * 36], s_rwl[32 * 36];   // [c][k] presplit
    __shared__ float s_gb[16], s_rb[32];
    __shared__ float s_scale[32], s_shift[32];
    __shared__ float s_st[2][32];

    int tid = threadIdx.x;
    int w = tid >> 5, l = tid & 31;
    int gr = l >> 2, gc = l & 3;
    int prt = blockIdx.x & (NPART - 1);
    int lp = tid;                        // local position
    int p = blockIdx.x * 64 + lp;
    int lrb = 32 * w;                    // warp's local position base
    int pb = blockIdx.x * 64;

    // ---- prefetch x/r (independent of everything below) ----
    float4 xr[16];
    #pragma unroll
    for (int cp = 0; cp < 16; cp++) xr[cp] = g_xr[cp * NPOS + p];

    // ---- stage + presplit weights into smem ----
    #pragma unroll
    for (int i = 0; i < 8; i++) {
        int idx = tid + i * 64;
        int j = idx >> 5, k = idx & 31;
        unsigned hi, lo;
        split_tf32(gate_w[layer * 512 + idx], hi, lo);
        s_gwh[j * 36 + k] = hi; s_gwl[j * 36 + k] = lo;
    }
    #pragma unroll
    for (int i = 0; i < 16; i++) {
        int idx = tid + i * 64;
        int c = idx >> 5, k = idx & 31;
        unsigned hi, lo;
        split_tf32(res_w[layer * 1024 + idx], hi, lo);
        s_rwh[c * 36 + k] = hi; s_rwl[c * 36 + k] = lo;
    }
    if (tid < 16) s_gb[tid] = gate_b[layer * 16 + tid];
    if (tid >= 32 && tid < 48) s_rb[tid - 32] = res_b[layer * 32 + tid - 32];
    if (tid >= 48 && tid < 64) s_rb[tid - 32] = res_b[layer * 32 + tid - 32];
    if (tid < 32) { s_st[0][tid] = 0.f; s_st[1][tid] = 0.f; }
    bn_combine32(bn_g + (layer - 1) * 32, bn_b + (layer - 1) * 32, layer - 1,
                 s_scale, s_shift, tid);
    __syncthreads();

    // ---- phase A: BN + residual from prefetched regs; x' -> gmem + sbuf ----
    float xn[32];
    #pragma unroll
    for (int cp = 0; cp < 16; cp++) {
        float4 v = xr[cp];
        float v0 = fmaf(s_scale[2 * cp],     v.z, v.x + s_shift[2 * cp]);
        float v1 = fmaf(s_scale[2 * cp + 1], v.w, v.y + s_shift[2 * cp + 1]);
        xn[2 * cp] = v0; xn[2 * cp + 1] = v1;
        *(float2*)&g_xr[(size_t)cp * NPOS + p] = make_float2(v0, v1);
    }
    #pragma unroll
    for (int qd = 0; qd < 8; qd++)
        *(float4*)&sbuf[lp * SBST + 4 * qd] =
            make_float4(xn[4 * qd], xn[4 * qd + 1], xn[4 * qd + 2], xn[4 * qd + 3]);
    __syncwarp();

    // ---- gate GEMM: D[32pos x 16ch], A = x (sbuf), B = gate_w presplit ----
    float gC[2][2][4];
    #pragma unroll
    for (int mt = 0; mt < 2; mt++)
        #pragma unroll
        for (int nt = 0; nt < 2; nt++) {
            float b0 = s_gb[nt * 8 + 2 * gc], b1 = s_gb[nt * 8 + 2 * gc + 1];
            gC[mt][nt][0] = b0; gC[mt][nt][1] = b1;
            gC[mt][nt][2] = b0; gC[mt][nt][3] = b1;
        }
    #pragma unroll
    for (int kt = 0; kt < 4; kt++) {
        unsigned ah[2][4], al[2][4];
        #pragma unroll
        for (int mt = 0; mt < 2; mt++) {
            int r0 = (lrb + mt * 16 + gr) * SBST + kt * 8 + gc;
            int r1 = r0 + 8 * SBST;
            split_tf32(sbuf[r0],     ah[mt][0], al[mt][0]);
            split_tf32(sbuf[r1],     ah[mt][1], al[mt][1]);
            split_tf32(sbuf[r0 + 4], ah[mt][2], al[mt][2]);
            split_tf32(sbuf[r1 + 4], ah[mt][3], al[mt][3]);
        }
        #pragma unroll
        for (int nt = 0; nt < 2; nt++) {
            int bi = (nt * 8 + gr) * 36 + kt * 8 + gc;
            unsigned bh0 = s_gwh[bi], bh1 = s_gwh[bi + 4];
            unsigned bl0 = s_gwl[bi], bl1 = s_gwl[bi + 4];
            #pragma unroll
            for (int mt = 0; mt < 2; mt++) {
                mma_tf32(gC[mt][nt], ah[mt], bh0, bh1);
                mma_tf32(gC[mt][nt], ah[mt], bl0, bl1);
                mma_tf32(gC[mt][nt], al[mt], bh0, bh1);
            }
        }
    }
    __syncwarp();   // gate A reads complete before cm overwrites sbuf

    // ---- concat-mish -> sbuf[pos][cm] (paired STS.64) ----
    #pragma unroll
    for (int mt = 0; mt < 2; mt++)
        #pragma unroll
        for (int nt = 0; nt < 2; nt++) {
            int j = nt * 8 + 2 * gc;
            int pos0 = lrb + mt * 16 + gr;
            float p0, n0, p1, n1;
            mish_pair(gC[mt][nt][0], p0, n0);
            mish_pair(gC[mt][nt][1], p1, n1);
            *(float2*)&sbuf[pos0 * SBST + j]      = make_float2(p0, p1);
            *(float2*)&sbuf[pos0 * SBST + j + 16] = make_float2(n0, n1);
            mish_pair(gC[mt][nt][2], p0, n0);
            mish_pair(gC[mt][nt][3], p1, n1);
            *(float2*)&sbuf[(pos0 + 8) * SBST + j]      = make_float2(p0, p1);
            *(float2*)&sbuf[(pos0 + 8) * SBST + j + 16] = make_float2(n0, n1);
        }
    __syncwarp();

    // ---- res GEMM: D[32pos x 32ch], A = cm (sbuf), B = res_w presplit ----
    float rC[2][4][4];
    #pragma unroll
    for (int mt = 0; mt < 2; mt++)
        #pragma unroll
        for (int nt = 0; nt < 4; nt++) {
            float b0 = s_rb[nt * 8 + 2 * gc], b1 = s_rb[nt * 8 + 2 * gc + 1];
            rC[mt][nt][0] = b0; rC[mt][nt][1] = b1;
            rC[mt][nt][2] = b0; rC[mt][nt][3] = b1;
        }
    #pragma unroll
    for (int kt = 0; kt < 4; kt++) {
        unsigned ah[2][4], al[2][4];
        #pragma unroll
        for (int mt = 0; mt < 2; mt++) {
            int r0 = (lrb + mt * 16 + gr) * SBST + kt * 8 + gc;
            int r1 = r0 + 8 * SBST;
            split_tf32(sbuf[r0],     ah[mt][0], al[mt][0]);
            split_tf32(sbuf[r1],     ah[mt][1], al[mt][1]);
            split_tf32(sbuf[r0 + 4], ah[mt][2], al[mt][2]);
            split_tf32(sbuf[r1 + 4], ah[mt][3], al[mt][3]);
        }
        #pragma unroll
        for (int nt = 0; nt < 4; nt++) {
            int bi = (nt * 8 + gr) * 36 + kt * 8 + gc;
            unsigned bh0 = s_rwh[bi], bh1 = s_rwh[bi + 4];
            unsigned bl0 = s_rwl[bi], bl1 = s_rwl[bi + 4];
            #pragma unroll
            for (int mt = 0; mt < 2; mt++) {
                mma_tf32(rC[mt][nt], ah[mt], bh0, bh1);
                mma_tf32(rC[mt][nt], ah[mt], bl0, bl1);
                mma_tf32(rC[mt][nt], al[mt], bh0, bh1);
            }
        }
    }

    // ---- store r (.zw of g_xr) + per-lane stat partials ----
    float s8[8], q8[8];
    #pragma unroll
    for (int i = 0; i < 8; i++) { s8[i] = 0.f; q8[i] = 0.f; }
    #pragma unroll
    for (int mt = 0; mt < 2; mt++)
        #pragma unroll
        for (int nt = 0; nt < 4; nt++) {
            int cp = nt * 4 + gc;                 // channel-pair index
            int pos0 = pb + lrb + mt * 16 + gr;
            float a0 = rC[mt][nt][0], a1 = rC[mt][nt][1];   // pos0, ch/ch+1
            float a2 = rC[mt][nt][2], a3 = rC[mt][nt][3];   // pos0+8
            *(float2*)((float*)&g_xr[(size_t)cp * NPOS + pos0] + 2) =
                make_float2(a0, a1);
            *(float2*)((float*)&g_xr[(size_t)cp * NPOS + pos0 + 8] + 2) =
                make_float2(a2, a3);
            int si = nt * 2;
            s8[si]     += a0 + a2;
            q8[si]      = fmaf(a0, a0, fmaf(a2, a2, q8[si]));
            s8[si + 1] += a1 + a3;
            q8[si + 1]  = fmaf(a1, a1, fmaf(a3, a3, q8[si + 1]));
        }
    // butterfly over gr (lane bits 2..4)
    #pragma unroll
    for (int d = 4; d < 32; d <<= 1) {
        #pragma unroll
        for (int i = 0; i < 8; i++) {
            s8[i] += __shfl_xor_sync(0xffffffffu, s8[i], d);
            q8[i] += __shfl_xor_sync(0xffffffffu, q8[i], d);
        }
    }
    if (gr == 0) {
        #pragma unroll
        for (int nt = 0; nt < 4; nt++)
            #pragma unroll
            for (int u = 0; u < 2; u++) {
                int c = nt * 8 + 2 * gc + u;
                atomicAdd(&s_st[0][c], s8[nt * 2 + u]);
                atomicAdd(&s_st[1][c], q8[nt * 2 + u]);
            }
    }
    __syncthreads();
    if (tid < 64) {
        int c = tid & 31, kind = tid >> 5;
        atomicAdd(stat_ptr(prt, layer, kind) + c, s_st[kind][c]);
    }
}

// apply BN(39) + residual -> final x into g_xf; stats[40]
__global__ __launch_bounds__(64, 7) void k_endA(
    const float* __restrict__ bn_g, const float* __restrict__ bn_b)
{
    __shared__ __align__(16) float4 s_red4[8 * 65];
    __shared__ __align__(16) float4 s_ps[64], s_pq[64];
    __shared__ float s_scale[32], s_shift[32];
    int tid = threadIdx.x;
    int p = blockIdx.x * 64 + tid;
    int prt = blockIdx.x & (NPART - 1);
    bn_combine32(bn_g + 39 * 32, bn_b + 39 * 32, 39, s_scale, s_shift, tid);
    __syncthreads();
    float xn[32];
    #pragma unroll
    for (int cp = 0; cp < 16; cp++) {
        float4 v = g_xr[cp * NPOS + p];
        xn[2 * cp]     = fmaf(s_scale[2 * cp],     v.z, v.x + s_shift[2 * cp]);
        xn[2 * cp + 1] = fmaf(s_scale[2 * cp + 1], v.w, v.y + s_shift[2 * cp + 1]);
    }
    #pragma unroll
    for (int cq = 0; cq < 8; cq++)
        g_xf[cq * NPOS + p] = make_float4(xn[4 * cq], xn[4 * cq + 1],
                                          xn[4 * cq + 2], xn[4 * cq + 3]);
    reduce64(s_red4, s_ps, s_pq, xn, tid, prt, 40);
}

// tiled end_conv1: z[128] = W1 @ concat_mish(bn1(x)); stats[41]
__global__ __launch_bounds__(256, 3) void k_endB(
    const float* __restrict__ bn1_g, const float* __restrict__ bn1_b,
    const float* __restrict__ w1, const float* __restrict__ b1)
{
    __shared__ __align__(16) float s_w[128 * 68];
    __shared__ __align__(16) float s_y[64 * 68];
    __shared__ float s_ps[128 * 17], s_pq[128 * 17];
    __shared__ float s_scale[32], s_shift[32];

    int tid = threadIdx.x;
    int p0 = blockIdx.x * 64;
    int prt = blockIdx.x & (NPART - 1);

    bn_combine32(bn1_g, bn1_b, 40, s_scale, s_shift, tid);

    #pragma unroll
    for (int i = tid * 4; i < 8192; i += 1024) {
        float4 v = *(const float4*)(w1 + i);
        int o = i >> 6, k = i & 63;
        *(float4*)&s_w[o * 68 + k] = v;
    }
    __syncthreads();

    #pragma unroll
    for (int it = 0; it < 2; it++) {
        int cq = (tid >> 6) + it * 4;
        int pos = tid & 63;
        float4 xq = g_xf[cq * NPOS + p0 + pos];
        float xv[4] = {xq.x, xq.y, xq.z, xq.w};
        #pragma unroll
        for (int u = 0; u < 4; u++) {
            int c = cq * 4 + u;
            float t = fmaf(s_scale[c], xv[u], s_shift[c]);
            float yp, yn;
            mish_pair(t, yp, yn);
            s_y[c * 68 + pos]        = yp;
            s_y[(c + 32) * 68 + pos] = yn;
        }
    }
    __syncthreads();

    int ty = tid >> 4;
    int tx = tid & 15;
    int o0 = ty * 8;
    u64 acc[8][2];
    #pragma unroll
    for (int i = 0; i < 8; i++) {
        u64 b = pack2(__ldg(b1 + o0 + i));
        acc[i][0] = b; acc[i][1] = b;
    }
    #pragma unroll 8
    for (int k = 0; k < 64; k++) {
        ulonglong2 yv = *(const ulonglong2*)&s_y[k * 68 + tx * 4];
        #pragma unroll
        for (int i = 0; i < 8; i++) {
            u64 w = pack2(s_w[(o0 + i) * 68 + k]);
            fma2(acc[i][0], w, yv.x, acc[i][0]);
            fma2(acc[i][1], w, yv.y, acc[i][1]);
        }
    }
    #pragma unroll
    for (int i = 0; i < 8; i++) {
        float a0 = lo2(acc[i][0]), a1 = hi2(acc[i][0]);
        float a2 = lo2(acc[i][1]), a3 = hi2(acc[i][1]);
        *(float4*)&g_z[(size_t)(o0 + i) * NPOS + p0 + tx * 4] =
            make_float4(a0, a1, a2, a3);
        s_ps[(o0 + i) * 17 + tx] = a0 + a1 + a2 + a3;
        s_pq[(o0 + i) * 17 + tx] =
            fmaf(a0, a0, fmaf(a1, a1, fmaf(a2, a2, a3 * a3)));
    }
    __syncthreads();
    {
        int o = tid & 127, kind = tid >> 7;
        const float* src = kind ? s_pq : s_ps;
        float t = 0.f;
        #pragma unroll
        for (int j = 0; j < 16; j++) t += src[o * 17 + j];
        atomicAdd(stat_ptr(prt, 41, kind) + o, t);
    }
}

// out = end_conv2 (256x256) @ concat_mish(bn2(z)); f32x2 packed FMA.
__global__ __launch_bounds__(256) void k_endC(
    const float* __restrict__ bn2_g, const float* __restrict__ bn2_b,
    const float* __restrict__ w2, const float* __restrict__ b2,
    float* __restrict__ out)
{
    __shared__ __align__(16) float sBuf[256 * 33 + 32 * 64];
    __shared__ float sSc[128], sSh[128], sB2[256];
    float* sW = sBuf;
    float* sV = sBuf + 256 * 33;

    int tid = threadIdx.x;
    int ty = tid >> 3;
    int tx = tid & 7;
    int p0 = blockIdx.x * 64;
    int l0 = p0 >> 3;

    if (tid < 128) {
        float s = 0.f, q = 0.f;
        #pragma unroll
        for (int pp = 0; pp < NPART; pp++) {
            s += g_statp[pp][41][0][tid];
            q += g_statp[pp][41][1][tid];
        }
        float m = s * (1.0f / NPOSf);
        float var = q * (1.0f / NPOSf) - m * m;
        float inv = rsqrtf(var + 1e-5f);
        float sc = bn2_g[tid] * inv;
        sSc[tid] = sc;
        sSh[tid] = bn2_b[tid] - m * sc;
    }
    sB2[tid] = b2[tid];

    u64 acc[8][4];
    #pragma unroll
    for (int i = 0; i < 8; i++)
        #pragma unroll
        for (int jp = 0; jp < 4; jp++) acc[i][jp] = 0ULL;

    for (int kc = 0; kc < 8; kc++) {
        __syncthreads();
        for (int idx = tid; idx < 8192; idx += 256) {
            int o = idx >> 5, k = idx & 31;
            sW[o * 33 + k] = w2[o * 256 + kc * 32 + k];
        }
        for (int idx = tid; idx < 2048; idx += 256) {
            int kk = idx >> 6, qq = idx & 63;
            int c = kc * 32 + kk;
            int zc = (c < 128) ? c : c - 128;
            float t = fmaf(sSc[zc], g_z[zc * NPOS + p0 + qq], sSh[zc]);
            sV[kk * 64 + qq] = mishf((c < 128) ? t : -t);
        }
        __syncthreads();
        int woff = ty * 8 * 33;
        int voff = tx * 8;
        #pragma unroll
        for (int k = 0; k < 32; k++) {
            u64 vv[4];
            #pragma unroll
            for (int jp = 0; jp < 4; jp++)
                vv[jp] = *(const u64*)&sV[k * 64 + voff + jp * 2];
            #pragma unroll
            for (int i = 0; i < 8; i++) {
                u64 wd = pack2(sW[woff + i * 33 + k]);
                #pragma unroll
                for (int jp = 0; jp < 4; jp++)
                    fma2(acc[i][jp], wd, vv[jp], acc[i][jp]);
            }
        }
    }

    for (int oh = 0; oh < 2; oh++) {
        __syncthreads();
        if ((ty >> 4) == oh) {
            int orow = (ty & 15) * 8;
            #pragma unroll
            for (int i = 0; i < 8; i++) {
                float bias = sB2[oh * 128 + orow + i];
                #pragma unroll
                for (int j = 0; j < 8; j++) {
                    int jp = j >> 1;
                    float f = (j & 1) ? hi2(acc[i][jp]) : lo2(acc[i][jp]);
                    sBuf[(orow + i) * 64 + j * 8 + tx] = f + bias;
                }
            }
        }
        __syncthreads();
        for (int idx = tid; idx < 2048; idx += 256) {
            int oloc = idx >> 4;
            int b = (idx >> 1) & 7;
            int hh = idx & 1;
            float4 v = *(float4*)&sBuf[oloc * 64 + b * 8 + hh * 4];
            *(float4*)&out[(size_t)b * 2097152 + (size_t)(oh * 128 + oloc) * 8192
                           + l0 + hh * 4] = v;
        }
    }
}

extern "C" void kernel_launch(void* const* d_in, const int* in_sizes, int n_in,
                              void* d_out, int out_size) {
    const float* x           = (const float*)d_in[0];
    const float* start_w     = (const float*)d_in[1];
    const float* start_b     = (const float*)d_in[2];
    const float* gate_w      = (const float*)d_in[3];
    const float* gate_b      = (const float*)d_in[4];
    const float* res_w       = (const float*)d_in[5];
    const float* res_b       = (const float*)d_in[6];
    const float* bn_g        = (const float*)d_in[7];
    const float* bn_b        = (const float*)d_in[8];
    const float* end_bn1_g   = (const float*)d_in[9];
    const float* end_bn1_b   = (const float*)d_in[10];
    const float* end_conv1_w = (const float*)d_in[11];
    const float* end_conv1_b = (const float*)d_in[12];
    const float* end_bn2_g   = (const float*)d_in[13];
    const float* end_bn2_b   = (const float*)d_in[14];
    const float* end_conv2_w = (const float*)d_in[15];
    const float* end_conv2_b = (const float*)d_in[16];
    float* out = (float*)d_out;

    k_prep<<<336, 512>>>();
    k_start<<<256, 256>>>(x, start_w, start_b, gate_w, gate_b, res_w, res_b);
    for (int i = 1; i < 40; i++)
        k_layer<<<1024, 64>>>(gate_w, gate_b, res_w, res_b, bn_g, bn_b, i);
    k_endA<<<1024, 64>>>(bn_g, bn_b);
    k_endB<<<1024, 256>>>(end_bn1_g, end_bn1_b, end_conv1_w, end_conv1_b);
    k_endC<<<1024, 256>>>(end_bn2_g, end_bn2_b, end_conv2_w, end_conv2_b, out);
}